// round 6
// baseline (speedup 1.0000x reference)
#include <cuda_runtime.h>
#include <cuda_bf16.h>
#include <cuda_fp16.h>
#include <math.h>
#include <stdint.h>

#define NNODES 100000
#define NEDGES 1600000
#define FIN 256
#define HID 128
#define COUT 64

#define SCAN_TPB 256
#define SCAN_ELEMS 8
#define SCAN_CHUNK (SCAN_TPB * SCAN_ELEMS)                 // 2048
#define SCAN_NB ((NNODES + SCAN_CHUNK - 1) / SCAN_CHUNK)   // 49

// ---------------- scratch (static __device__, no allocation) ----------------
__device__ __half g_tmp[NNODES * HID];          // GEMM output (messages), fp16
__device__ __nv_bfloat16 g_ah[NNODES * HID];    // relu'd h, hi split (GEMM input)
__device__ __nv_bfloat16 g_al[NNODES * HID];    // relu'd h, lo split
__device__ __nv_bfloat16 g_ph[NNODES * HID];    // pre-relu h2, hi split (gram)
__device__ __nv_bfloat16 g_pl[NNODES * HID];    // pre-relu h2, lo split
__device__ float g_dinv[NNODES];
__device__ int   g_cnt[NNODES];
__device__ int   g_cursor[NNODES];
__device__ int   g_rowptr[NNODES + 1];
__device__ int   g_col[NEDGES];
__device__ float g_w[NEDGES];
__device__ float g_G[HID * HID];
__device__ float g_csum[HID];
__device__ int   g_bsum[SCAN_NB];

// split-bf16 transposed weights: Wt[d][k] = W[k][d]
__device__ __nv_bfloat16 g_w0h[HID * FIN],  g_w0l[HID * FIN];
__device__ __nv_bfloat16 g_w1h[HID * HID],  g_w1l[HID * HID];
__device__ __nv_bfloat16 g_w2h[HID * HID],  g_w2l[HID * HID];
__device__ __nv_bfloat16 g_w3h[COUT * HID], g_w3l[COUT * HID];

// ---------------- helpers ----------------
__device__ __forceinline__ uint32_t smem_u32(const void* p) {
    uint32_t a;
    asm("{ .reg .u64 t; cvta.to.shared.u64 t, %1; cvt.u32.u64 %0, t; }"
        : "=r"(a) : "l"(p));
    return a;
}
__device__ __forceinline__ uint32_t sw128(uint32_t off) {
    return off ^ ((off >> 3) & 0x70);
}
__device__ __forceinline__ void ldsm4(uint32_t* r, uint32_t addr) {
    asm volatile("ldmatrix.sync.aligned.m8n8.x4.shared.b16 {%0,%1,%2,%3}, [%4];"
                 : "=r"(r[0]), "=r"(r[1]), "=r"(r[2]), "=r"(r[3]) : "r"(addr));
}
__device__ __forceinline__ void mma16816(float* c, const uint32_t* a,
                                         const uint32_t* b) {
    asm volatile(
        "mma.sync.aligned.m16n8k16.row.col.f32.bf16.bf16.f32 "
        "{%0,%1,%2,%3}, {%4,%5,%6,%7}, {%8,%9}, {%0,%1,%2,%3};"
        : "+f"(c[0]), "+f"(c[1]), "+f"(c[2]), "+f"(c[3])
        : "r"(a[0]), "r"(a[1]), "r"(a[2]), "r"(a[3]), "r"(b[0]), "r"(b[1]));
}
__device__ __forceinline__ void split2(float f, __nv_bfloat16& h, __nv_bfloat16& l) {
    h = __float2bfloat16_rn(f);
    l = __float2bfloat16_rn(f - __bfloat162float(h));
}

// ---------------- preprocessing ----------------
__global__ void k_zero_init() {
    int i = blockIdx.x * blockDim.x + threadIdx.x;
    if (i < NNODES) { g_cnt[i] = 0; g_cursor[i] = 0; }
}

__global__ void k_zero_G() {
    int i = blockIdx.x * blockDim.x + threadIdx.x;
    if (i < HID * HID) g_G[i] = 0.f;
    if (i < HID) g_csum[i] = 0.f;
}

__global__ void k_count(const int* __restrict__ ei) {
    int e = blockIdx.x * blockDim.x + threadIdx.x;
    if (e < NEDGES) atomicAdd(&g_cnt[ei[e]], 1);
}

__global__ void k_dinv() {
    int i = blockIdx.x * blockDim.x + threadIdx.x;
    if (i < NNODES) g_dinv[i] = rsqrtf((float)(g_cnt[i] + 1));  // +1 self loop
}

__global__ void k_scan1() {
    __shared__ int warp_s[SCAN_TPB / 32];
    int tid = threadIdx.x, blk = blockIdx.x;
    int base = blk * SCAN_CHUNK + tid * SCAN_ELEMS;
    int s = 0;
#pragma unroll
    for (int i = 0; i < SCAN_ELEMS; i++) {
        int idx = base + i;
        if (idx < NNODES) s += g_cnt[idx];
    }
    for (int o = 16; o > 0; o >>= 1) s += __shfl_down_sync(0xffffffffu, s, o);
    if ((tid & 31) == 0) warp_s[tid >> 5] = s;
    __syncthreads();
    if (tid < SCAN_TPB / 32) {
        int w = warp_s[tid];
        for (int o = (SCAN_TPB / 64); o > 0; o >>= 1)
            w += __shfl_down_sync(0xffu, w, o);
        if (tid == 0) g_bsum[blk] = w;
    }
}

__global__ void k_scan2() {
    __shared__ int sh[64];
    int tid = threadIdx.x;
    sh[tid] = (tid < SCAN_NB) ? g_bsum[tid] : 0;
    __syncthreads();
    for (int o = 1; o < 64; o <<= 1) {
        int v = (tid >= o) ? sh[tid - o] : 0;
        __syncthreads();
        sh[tid] += v;
        __syncthreads();
    }
    if (tid < SCAN_NB) g_bsum[tid] = (tid == 0) ? 0 : sh[tid - 1];
    if (tid == 0) g_rowptr[NNODES] = sh[SCAN_NB - 1];
}

__global__ void k_scan3() {
    __shared__ int tsum[SCAN_TPB];
    int tid = threadIdx.x, blk = blockIdx.x;
    int base = blk * SCAN_CHUNK + tid * SCAN_ELEMS;
    int c[SCAN_ELEMS];
    int s = 0;
#pragma unroll
    for (int i = 0; i < SCAN_ELEMS; i++) {
        int idx = base + i;
        c[i] = (idx < NNODES) ? g_cnt[idx] : 0;
        s += c[i];
    }
    tsum[tid] = s;
    __syncthreads();
    for (int o = 1; o < SCAN_TPB; o <<= 1) {
        int v = (tid >= o) ? tsum[tid - o] : 0;
        __syncthreads();
        tsum[tid] += v;
        __syncthreads();
    }
    int run = g_bsum[blk] + ((tid == 0) ? 0 : tsum[tid - 1]);
#pragma unroll
    for (int i = 0; i < SCAN_ELEMS; i++) {
        int idx = base + i;
        if (idx < NNODES) { g_rowptr[idx] = run; run += c[i]; }
    }
}

__global__ void k_fill(const int* __restrict__ ei) {
    int e = blockIdx.x * blockDim.x + threadIdx.x;
    if (e >= NEDGES) return;
    int r = ei[e];
    int c = ei[NEDGES + e];
    int pos = g_rowptr[r] + atomicAdd(&g_cursor[r], 1);
    g_col[pos] = c;
    g_w[pos] = g_dinv[r] * g_dinv[c];
}

// ---------------- weight prep: W[K,D] fp32 -> Wt hi/lo bf16 [D][K] ----------
template <int K, int D>
__global__ void k_prepW(const float* __restrict__ W,
                        __nv_bfloat16* __restrict__ Wh,
                        __nv_bfloat16* __restrict__ Wl) {
    int i = blockIdx.x * blockDim.x + threadIdx.x;
    if (i >= K * D) return;
    int n = i / K, k = i % K;
    float v = W[k * D + n];
    __nv_bfloat16 h, l;
    split2(v, h, l);
    Wh[n * K + k] = h;
    Wl[n * K + k] = l;
}

// ---------------- tensor-core split-bf16 GEMM: C = A[N,K] @ W[K,D] ---------
// 512 threads, 16 warps as 4x4. CTA tile 128 x D; warp tile 32 x D/4.
// CONVERT: A is fp32 (layer 0); else A pre-split bf16 hi/lo (already relu'd).
// Output fp16 messages.
template <int K, int D, bool CONVERT>
__global__ __launch_bounds__(512) void k_tgemm512(const float* __restrict__ Af,
                                                  const __nv_bfloat16* __restrict__ Ah,
                                                  const __nv_bfloat16* __restrict__ Al,
                                                  const __nv_bfloat16* __restrict__ Bh,
                                                  const __nv_bfloat16* __restrict__ Bl,
                                                  __half* __restrict__ C) {
    extern __shared__ __align__(1024) uint8_t smem[];
    const int CK = 64;                   // K elems per chunk
    const int NCH = K / CK;
    const int WN = D / 4;                // 32 (D=128) or 16 (D=64)
    const int NT = WN / 8;               // 4 or 2
    const int OFF_AH = 0;
    const int OFF_AL = 128 * 128;        // 16 KB per A buffer
    const int OFF_BH = 2 * 128 * 128;
    const int OFF_BL = OFF_BH + D * 128;

    uint32_t sb = smem_u32(smem);
    int tid = threadIdx.x, wid = tid >> 5, lane = tid & 31;
    int wm = wid & 3, wn = wid >> 2;
    int row0 = wm * 32;
    int col0 = wn * WN;
    int grow = blockIdx.x * 128;

    float acc[2][NT][4];
#pragma unroll
    for (int i = 0; i < 2; i++)
#pragma unroll
        for (int j = 0; j < NT; j++)
#pragma unroll
            for (int q = 0; q < 4; q++) acc[i][j][q] = 0.f;

    for (int ch = 0; ch < NCH; ch++) {
        int kk = ch * CK;
        // ---- A chunk: 128 rows x 64 bf16 hi/lo, swizzled
        if (CONVERT) {
#pragma unroll
            for (int i = 0; i < 2; i++) {
                int u = tid + i * 512;
                int m = u >> 3, g = u & 7;
                int r = grow + m;
                float4 v0 = make_float4(0.f, 0.f, 0.f, 0.f), v1 = v0;
                if (r < NNODES) {
                    const float* p = &Af[(size_t)r * K + kk + g * 8];
                    v0 = *(const float4*)p;
                    v1 = *(const float4*)(p + 4);
                }
                float f[8] = {v0.x, v0.y, v0.z, v0.w, v1.x, v1.y, v1.z, v1.w};
                uint32_t hp[4], lp[4];
#pragma unroll
                for (int j = 0; j < 4; j++) {
                    __nv_bfloat16 h0, l0, h1, l1;
                    split2(f[2 * j], h0, l0);
                    split2(f[2 * j + 1], h1, l1);
                    hp[j] = (uint32_t)__bfloat16_as_ushort(h0)
                          | ((uint32_t)__bfloat16_as_ushort(h1) << 16);
                    lp[j] = (uint32_t)__bfloat16_as_ushort(l0)
                          | ((uint32_t)__bfloat16_as_ushort(l1) << 16);
                }
                uint32_t so = sw128((uint32_t)(m * 128 + g * 16));
                *(uint4*)(smem + OFF_AH + so) = make_uint4(hp[0], hp[1], hp[2], hp[3]);
                *(uint4*)(smem + OFF_AL + so) = make_uint4(lp[0], lp[1], lp[2], lp[3]);
            }
        } else {
#pragma unroll
            for (int i = 0; i < 2; i++) {
                int u = tid + i * 512;
                int m = u >> 3, g = u & 7;
                int r = grow + m;
                uint4 hv = make_uint4(0, 0, 0, 0), lv = hv;
                if (r < NNODES) {
                    hv = *(const uint4*)&Ah[(size_t)r * K + kk + g * 8];
                    lv = *(const uint4*)&Al[(size_t)r * K + kk + g * 8];
                }
                uint32_t so = sw128((uint32_t)(m * 128 + g * 16));
                *(uint4*)(smem + OFF_AH + so) = hv;
                *(uint4*)(smem + OFF_AL + so) = lv;
            }
        }
        // ---- B chunk: D rows x 64 bf16 (pre-split), swizzled
#pragma unroll
        for (int i = 0; i < (D * 8 + 511) / 512; i++) {
            int u = tid + i * 512;
            if (u < D * 8) {
                int n = u >> 3, g = u & 7;
                uint32_t so = sw128((uint32_t)(n * 128 + g * 16));
                *(uint4*)(smem + OFF_BH + so) = *(const uint4*)&Bh[n * K + kk + g * 8];
                *(uint4*)(smem + OFF_BL + so) = *(const uint4*)&Bl[n * K + kk + g * 8];
            }
        }
        __syncthreads();
#pragma unroll
        for (int k16 = 0; k16 < CK / 16; k16++) {
            int kb = k16 * 32;               // byte offset of this k16 in row
            uint32_t ah[2][4], al[2][4];
#pragma unroll
            for (int mt = 0; mt < 2; mt++) {
                int r = row0 + mt * 16 + (lane & 15);
                int cb = kb + ((lane & 16) ? 16 : 0);
                uint32_t so = sw128((uint32_t)(r * 128 + cb));
                ldsm4(ah[mt], sb + OFF_AH + so);
                ldsm4(al[mt], sb + OFF_AL + so);
            }
#pragma unroll
            for (int bt = 0; bt < NT / 2; bt++) {
                int n = col0 + bt * 16 + (lane & 7) + ((lane & 16) ? 8 : 0);
                int cb = kb + ((lane & 8) ? 16 : 0);
                uint32_t so = sw128((uint32_t)(n * 128 + cb));
                uint32_t bh[4], bl[4];
                ldsm4(bh, sb + OFF_BH + so);
                ldsm4(bl, sb + OFF_BL + so);
#pragma unroll
                for (int h = 0; h < 2; h++) {
                    int nt = bt * 2 + h;
#pragma unroll
                    for (int mt = 0; mt < 2; mt++) {
                        mma16816(acc[mt][nt], ah[mt], &bh[h * 2]);
                        mma16816(acc[mt][nt], ah[mt], &bl[h * 2]);
                        mma16816(acc[mt][nt], al[mt], &bh[h * 2]);
                    }
                }
            }
        }
        __syncthreads();
    }
    // ---- epilogue: fragment -> global fp16 (half2 per store)
#pragma unroll
    for (int mt = 0; mt < 2; mt++) {
        int r0 = grow + row0 + mt * 16 + (lane >> 2);
        int r1 = r0 + 8;
#pragma unroll
        for (int nt = 0; nt < NT; nt++) {
            int cc = col0 + nt * 8 + (lane & 3) * 2;
            if (r0 < NNODES)
                *(__half2*)&C[(size_t)r0 * D + cc] =
                    __floats2half2_rn(acc[mt][nt][0], acc[mt][nt][1]);
            if (r1 < NNODES)
                *(__half2*)&C[(size_t)r1 * D + cc] =
                    __floats2half2_rn(acc[mt][nt][2], acc[mt][nt][3]);
        }
    }
}

// ---------------- sparse aggregation (fp16 gather, fp32 accumulate) --------
// h[i] = dinv[i]^2 * tmp[i] + sum_e w_e * tmp[col_e]; writes relu(h) as
// split bf16 (GEMM operand); PRE also stores pre-relu split (gram operand).
template <bool PRE>
__global__ void k_agg128s(const __half* __restrict__ tmp,
                          __nv_bfloat16* __restrict__ ah,
                          __nv_bfloat16* __restrict__ al,
                          __nv_bfloat16* __restrict__ ph,
                          __nv_bfloat16* __restrict__ pl) {
    int gw = (blockIdx.x * blockDim.x + threadIdx.x) >> 5;
    int lane = threadIdx.x & 31;
    if (gw >= NNODES) return;
    const uint2* __restrict__ t = (const uint2*)tmp;   // 4 halves per lane
    float di = g_dinv[gw];
    float s = di * di;
    uint2 u = t[gw * 32 + lane];
    float2 p0 = __half22float2(*(__half2*)&u.x);
    float2 p1 = __half22float2(*(__half2*)&u.y);
    float4 acc = make_float4(p0.x * s, p0.y * s, p1.x * s, p1.y * s);
    float4 acc2 = make_float4(0.f, 0.f, 0.f, 0.f);
    int e = g_rowptr[gw], en = g_rowptr[gw + 1];
    for (; e + 1 < en; e += 2) {
        int c0 = g_col[e], c1 = g_col[e + 1];
        float w0 = g_w[e], w1 = g_w[e + 1];
        uint2 a = t[c0 * 32 + lane];
        uint2 b = t[c1 * 32 + lane];
        float2 a0 = __half22float2(*(__half2*)&a.x);
        float2 a1 = __half22float2(*(__half2*)&a.y);
        float2 b0 = __half22float2(*(__half2*)&b.x);
        float2 b1 = __half22float2(*(__half2*)&b.y);
        acc.x = fmaf(w0, a0.x, acc.x);   acc.y = fmaf(w0, a0.y, acc.y);
        acc.z = fmaf(w0, a1.x, acc.z);   acc.w = fmaf(w0, a1.y, acc.w);
        acc2.x = fmaf(w1, b0.x, acc2.x); acc2.y = fmaf(w1, b0.y, acc2.y);
        acc2.z = fmaf(w1, b1.x, acc2.z); acc2.w = fmaf(w1, b1.y, acc2.w);
    }
    if (e < en) {
        int c0 = g_col[e];
        float w0 = g_w[e];
        uint2 a = t[c0 * 32 + lane];
        float2 a0 = __half22float2(*(__half2*)&a.x);
        float2 a1 = __half22float2(*(__half2*)&a.y);
        acc.x = fmaf(w0, a0.x, acc.x); acc.y = fmaf(w0, a0.y, acc.y);
        acc.z = fmaf(w0, a1.x, acc.z); acc.w = fmaf(w0, a1.y, acc.w);
    }
    acc.x += acc2.x; acc.y += acc2.y; acc.z += acc2.z; acc.w += acc2.w;

    float f[4] = {acc.x, acc.y, acc.z, acc.w};
    size_t base = (size_t)gw * HID + lane * 4;
    if (PRE) {
        ushort hh[4], ll[4];
#pragma unroll
        for (int j = 0; j < 4; j++) {
            __nv_bfloat16 h, l;
            split2(f[j], h, l);
            hh[j] = __bfloat16_as_ushort(h);
            ll[j] = __bfloat16_as_ushort(l);
        }
        *(uint2*)&ph[base] = make_uint2((uint32_t)hh[0] | ((uint32_t)hh[1] << 16),
                                        (uint32_t)hh[2] | ((uint32_t)hh[3] << 16));
        *(uint2*)&pl[base] = make_uint2((uint32_t)ll[0] | ((uint32_t)ll[1] << 16),
                                        (uint32_t)ll[2] | ((uint32_t)ll[3] << 16));
    }
    ushort rh[4], rl[4];
#pragma unroll
    for (int j = 0; j < 4; j++) {
        float v = fmaxf(f[j], 0.f);
        __nv_bfloat16 h, l;
        split2(v, h, l);
        rh[j] = __bfloat16_as_ushort(h);
        rl[j] = __bfloat16_as_ushort(l);
    }
    *(uint2*)&ah[base] = make_uint2((uint32_t)rh[0] | ((uint32_t)rh[1] << 16),
                                    (uint32_t)rh[2] | ((uint32_t)rh[3] << 16));
    *(uint2*)&al[base] = make_uint2((uint32_t)rl[0] | ((uint32_t)rl[1] << 16),
                                    (uint32_t)rl[2] | ((uint32_t)rl[3] << 16));
}

__global__ void k_agg64h(const __half* __restrict__ tmp, float* __restrict__ out) {
    int gw = (blockIdx.x * blockDim.x + threadIdx.x) >> 5;
    int lane = threadIdx.x & 31;
    if (gw >= NNODES) return;
    const uint32_t* __restrict__ t = (const uint32_t*)tmp;  // 2 halves per lane
    float di = g_dinv[gw];
    float s = di * di;
    uint32_t u = t[gw * 32 + lane];
    float2 p = __half22float2(*(__half2*)&u);
    float2 acc = make_float2(p.x * s, p.y * s);
    float2 acc2 = make_float2(0.f, 0.f);
    int e = g_rowptr[gw], en = g_rowptr[gw + 1];
    for (; e + 1 < en; e += 2) {
        int c0 = g_col[e], c1 = g_col[e + 1];
        float w0 = g_w[e], w1 = g_w[e + 1];
        uint32_t a = t[c0 * 32 + lane];
        uint32_t b = t[c1 * 32 + lane];
        float2 af = __half22float2(*(__half2*)&a);
        float2 bf = __half22float2(*(__half2*)&b);
        acc.x = fmaf(w0, af.x, acc.x);   acc.y = fmaf(w0, af.y, acc.y);
        acc2.x = fmaf(w1, bf.x, acc2.x); acc2.y = fmaf(w1, bf.y, acc2.y);
    }
    if (e < en) {
        int c0 = g_col[e];
        float w0 = g_w[e];
        uint32_t a = t[c0 * 32 + lane];
        float2 af = __half22float2(*(__half2*)&a);
        acc.x = fmaf(w0, af.x, acc.x); acc.y = fmaf(w0, af.y, acc.y);
    }
    acc.x += acc2.x; acc.y += acc2.y;
    ((float2*)out)[gw * 32 + lane] = acc;
}

// ---------------- Gram via mma from pre-split bf16 h2 (D=128) ---------------
__global__ __launch_bounds__(256) void k_gram_split(const __nv_bfloat16* __restrict__ ph,
                                                    const __nv_bfloat16* __restrict__ pl) {
    const int D = HID;
    __shared__ __align__(1024) uint8_t sm[2 * D * 128];
    const int OFF_L = D * 128;
    const int FG = D / 4;            // 32 feature groups
    const int PAIRS = 256 / FG;      // 8 row-pairs per pass
    const int NT = D / 8;            // 16
    const int MW = D / 16;           // 8 compute warps
    uint32_t sb = smem_u32(sm);
    int tid = threadIdx.x, wid = tid >> 5, lane = tid & 31;
    int f4 = tid % FG;
    int rp0 = tid / FG;

    float acc[NT][4];
#pragma unroll
    for (int j = 0; j < NT; j++)
#pragma unroll
        for (int q = 0; q < 4; q++) acc[j][q] = 0.f;
    float cs0 = 0.f, cs1 = 0.f, cs2 = 0.f, cs3 = 0.f;

    const int NCHUNK = (NNODES + 63) / 64;
    for (int ch = blockIdx.x; ch < NCHUNK; ch += gridDim.x) {
        int rbase = ch * 64;
#pragma unroll
        for (int it = 0; it < 32 / PAIRS; it++) {
            int pr = rp0 + it * PAIRS;
            int r0 = rbase + pr * 2, r1 = r0 + 1;
            uint2 h0v = make_uint2(0, 0), h1v = h0v, l0v = h0v, l1v = h0v;
            if (r0 < NNODES) {
                h0v = *(const uint2*)&ph[(size_t)r0 * D + f4 * 4];
                l0v = *(const uint2*)&pl[(size_t)r0 * D + f4 * 4];
            }
            if (r1 < NNODES) {
                h1v = *(const uint2*)&ph[(size_t)r1 * D + f4 * 4];
                l1v = *(const uint2*)&pl[(size_t)r1 * D + f4 * 4];
            }
            const ushort* h0s = (const ushort*)&h0v;
            const ushort* h1s = (const ushort*)&h1v;
            const ushort* l0s = (const ushort*)&l0v;
            const ushort* l1s = (const ushort*)&l1v;
            float fs[4];
#pragma unroll
            for (int j = 0; j < 4; j++) {
                fs[j] = __bfloat162float(__ushort_as_bfloat16(h0s[j]))
                      + __bfloat162float(__ushort_as_bfloat16(l0s[j]))
                      + __bfloat162float(__ushort_as_bfloat16(h1s[j]))
                      + __bfloat162float(__ushort_as_bfloat16(l1s[j]));
                int feat = f4 * 4 + j;
                uint32_t hp = (uint32_t)h0s[j] | ((uint32_t)h1s[j] << 16);
                uint32_t lp = (uint32_t)l0s[j] | ((uint32_t)l1s[j] << 16);
                uint32_t so = sw128((uint32_t)(feat * 128 + pr * 4));
                *(uint32_t*)(sm + so) = hp;
                *(uint32_t*)(sm + OFF_L + so) = lp;
            }
            cs0 += fs[0]; cs1 += fs[1]; cs2 += fs[2]; cs3 += fs[3];
        }
        __syncthreads();
        if (wid < MW) {
#pragma unroll
            for (int k16 = 0; k16 < 4; k16++) {
                int kb = k16 * 32;
                uint32_t ah[4], al[4];
                {
                    int r = wid * 16 + (lane & 15);
                    int cb = kb + ((lane & 16) ? 16 : 0);
                    uint32_t so = sw128((uint32_t)(r * 128 + cb));
                    ldsm4(ah, sb + so);
                    ldsm4(al, sb + OFF_L + so);
                }
#pragma unroll
                for (int bt = 0; bt < NT / 2; bt++) {
                    int n = bt * 16 + (lane & 7) + ((lane & 16) ? 8 : 0);
                    int cb = kb + ((lane & 8) ? 16 : 0);
                    uint32_t so = sw128((uint32_t)(n * 128 + cb));
                    uint32_t bh[4], bl[4];
                    ldsm4(bh, sb + so);
                    ldsm4(bl, sb + OFF_L + so);
#pragma unroll
                    for (int hh = 0; hh < 2; hh++) {
                        int nt = bt * 2 + hh;
                        mma16816(acc[nt], ah, &bh[hh * 2]);
                        mma16816(acc[nt], ah, &bl[hh * 2]);
                        mma16816(acc[nt], al, &bh[hh * 2]);
                    }
                }
            }
        }
        __syncthreads();
    }
    if (wid < MW) {
        int mrow = wid * 16 + (lane >> 2);
#pragma unroll
        for (int nt = 0; nt < NT; nt++) {
            int c = nt * 8 + (lane & 3) * 2;
            atomicAdd(&g_G[mrow * D + c], acc[nt][0]);
            atomicAdd(&g_G[mrow * D + c + 1], acc[nt][1]);
            atomicAdd(&g_G[(mrow + 8) * D + c], acc[nt][2]);
            atomicAdd(&g_G[(mrow + 8) * D + c + 1], acc[nt][3]);
        }
    }
    atomicAdd(&g_csum[f4 * 4 + 0], cs0);
    atomicAdd(&g_csum[f4 * 4 + 1], cs1);
    atomicAdd(&g_csum[f4 * 4 + 2], cs2);
    atomicAdd(&g_csum[f4 * 4 + 3], cs3);
}

// ---------------- Gram via mma from fp32 (D=64, for h3/out) -----------------
template <int D>
__global__ __launch_bounds__(256) void k_gram_mma(const float* __restrict__ h) {
    __shared__ __align__(1024) uint8_t sm[2 * D * 128];
    const int OFF_L = D * 128;
    const int FG = D / 4;
    const int PAIRS = 256 / FG;
    const int NT = D / 8;
    const int MW = D / 16;
    uint32_t sb = smem_u32(sm);
    int tid = threadIdx.x, wid = tid >> 5, lane = tid & 31;
    int f4 = tid % FG;
    int rp0 = tid / FG;

    float acc[NT][4];
#pragma unroll
    for (int j = 0; j < NT; j++)
#pragma unroll
        for (int q = 0; q < 4; q++) acc[j][q] = 0.f;
    float cs0 = 0.f, cs1 = 0.f, cs2 = 0.f, cs3 = 0.f;

    const int NCHUNK = (NNODES + 63) / 64;
    for (int ch = blockIdx.x; ch < NCHUNK; ch += gridDim.x) {
        int rbase = ch * 64;
#pragma unroll
        for (int it = 0; it < 32 / PAIRS; it++) {
            int pr = rp0 + it * PAIRS;
            int r0 = rbase + pr * 2, r1 = r0 + 1;
            float4 v0 = make_float4(0.f, 0.f, 0.f, 0.f), v1 = v0;
            if (r0 < NNODES) v0 = *(const float4*)&h[(size_t)r0 * D + f4 * 4];
            if (r1 < NNODES) v1 = *(const float4*)&h[(size_t)r1 * D + f4 * 4];
            cs0 += v0.x + v1.x; cs1 += v0.y + v1.y;
            cs2 += v0.z + v1.z; cs3 += v0.w + v1.w;
            float a0[4] = {v0.x, v0.y, v0.z, v0.w};
            float a1[4] = {v1.x, v1.y, v1.z, v1.w};
#pragma unroll
            for (int j = 0; j < 4; j++) {
                int feat = f4 * 4 + j;
                __nv_bfloat16 h0, l0, h1, l1;
                split2(a0[j], h0, l0);
                split2(a1[j], h1, l1);
                uint32_t hp = (uint32_t)__bfloat16_as_ushort(h0)
                            | ((uint32_t)__bfloat16_as_ushort(h1) << 16);
                uint32_t lp = (uint32_t)__bfloat16_as_ushort(l0)
                            | ((uint32_t)__bfloat16_as_ushort(l1) << 16);
                uint32_t so = sw128((uint32_t)(feat * 128 + pr * 4));
                *(uint32_t*)(sm + so) = hp;
                *(uint32_t*)(sm + OFF_L + so) = lp;
            }
        }
        __syncthreads();
        if (wid < MW) {
#pragma unroll
            for (int k16 = 0; k16 < 4; k16++) {
                int kb = k16 * 32;
                uint32_t ah[4], al[4];
                {
                    int r = wid * 16 + (lane & 15);
                    int cb = kb + ((lane & 16) ? 16 : 0);
                    uint32_t so = sw128((uint32_t)(r * 128 + cb));
                    ldsm4(ah, sb + so);
                    ldsm4(al, sb + OFF_L + so);
                }
#pragma unroll
                for (int bt = 0; bt < NT / 2; bt++) {
                    int n = bt * 16 + (lane & 7) + ((lane & 16) ? 8 : 0);
                    int cb = kb + ((lane & 8) ? 16 : 0);
                    uint32_t so = sw128((uint32_t)(n * 128 + cb));
                    uint32_t bh[4], bl[4];
                    ldsm4(bh, sb + so);
                    ldsm4(bl, sb + OFF_L + so);
#pragma unroll
                    for (int hh = 0; hh < 2; hh++) {
                        int nt = bt * 2 + hh;
                        mma16816(acc[nt], ah, &bh[hh * 2]);
                        mma16816(acc[nt], ah, &bl[hh * 2]);
                        mma16816(acc[nt], al, &bh[hh * 2]);
                    }
                }
            }
        }
        __syncthreads();
    }
    if (wid < MW) {
        int mrow = wid * 16 + (lane >> 2);
#pragma unroll
        for (int nt = 0; nt < NT; nt++) {
            int c = nt * 8 + (lane & 3) * 2;
            atomicAdd(&g_G[mrow * D + c], acc[nt][0]);
            atomicAdd(&g_G[mrow * D + c + 1], acc[nt][1]);
            atomicAdd(&g_G[(mrow + 8) * D + c], acc[nt][2]);
            atomicAdd(&g_G[(mrow + 8) * D + c + 1], acc[nt][3]);
        }
    }
    atomicAdd(&g_csum[f4 * 4 + 0], cs0);
    atomicAdd(&g_csum[f4 * 4 + 1], cs1);
    atomicAdd(&g_csum[f4 * 4 + 2], cs2);
    atomicAdd(&g_csum[f4 * 4 + 3], cs3);
}

// ---------------- correlation metric finalize (single block) ----------------
template <int D>
__global__ void k_finalize(float* __restrict__ dst) {
    __shared__ float sd[D];
    __shared__ float red[256];
    int tid = threadIdx.x;
    const float invN = 1.0f / (float)NNODES;
    if (tid < D) {
        float cjj = g_G[tid * D + tid] - g_csum[tid] * g_csum[tid] * invN;
        sd[tid] = sqrtf(fmaxf(cjj, 1e-12f));
    }
    __syncthreads();
    float sum = 0.f;
    for (int idx = tid; idx < D * D; idx += 256) {
        int j = idx / D, k = idx % D;
        if (k > j) {
            float cov = g_G[idx] - g_csum[j] * g_csum[k] * invN;
            sum += fabsf(cov / (sd[j] * sd[k]));
        }
    }
    red[tid] = sum;
    __syncthreads();
    for (int off = 128; off > 0; off >>= 1) {
        if (tid < off) red[tid] += red[tid + off];
        __syncthreads();
    }
    if (tid == 0) *dst = red[0] / (float)(D * (D - 1) / 2);
}

// ---------------- launch ----------------
extern "C" void kernel_launch(void* const* d_in, const int* in_sizes, int n_in,
                              void* d_out, int out_size) {
    const float* x  = (const float*)d_in[0];
    const int*   ei = (const int*)d_in[1];
    const float* W0 = (const float*)d_in[2];
    const float* W1 = (const float*)d_in[3];
    const float* W2 = (const float*)d_in[4];
    const float* W3 = (const float*)d_in[5];
    float* out = (float*)d_out;

    __half* tmp;
    __nv_bfloat16 *ah, *al, *ph, *pl;
    cudaGetSymbolAddress((void**)&tmp, g_tmp);
    cudaGetSymbolAddress((void**)&ah, g_ah);
    cudaGetSymbolAddress((void**)&al, g_al);
    cudaGetSymbolAddress((void**)&ph, g_ph);
    cudaGetSymbolAddress((void**)&pl, g_pl);
    __nv_bfloat16 *w0h, *w0l, *w1h, *w1l, *w2h, *w2l, *w3h, *w3l;
    cudaGetSymbolAddress((void**)&w0h, g_w0h); cudaGetSymbolAddress((void**)&w0l, g_w0l);
    cudaGetSymbolAddress((void**)&w1h, g_w1h); cudaGetSymbolAddress((void**)&w1l, g_w1l);
    cudaGetSymbolAddress((void**)&w2h, g_w2h); cudaGetSymbolAddress((void**)&w2l, g_w2l);
    cudaGetSymbolAddress((void**)&w3h, g_w3h); cudaGetSymbolAddress((void**)&w3l, g_w3l);

    const int SM_BIG = 2 * 128 * 128 + 2 * HID * 128;   // 65536
    const int SM_SML = 2 * 128 * 128 + 2 * COUT * 128;  // 49152
    cudaFuncSetAttribute(k_tgemm512<FIN, HID, true>,
                         cudaFuncAttributeMaxDynamicSharedMemorySize, SM_BIG);
    cudaFuncSetAttribute(k_tgemm512<HID, HID, false>,
                         cudaFuncAttributeMaxDynamicSharedMemorySize, SM_BIG);
    cudaFuncSetAttribute(k_tgemm512<HID, COUT, false>,
                         cudaFuncAttributeMaxDynamicSharedMemorySize, SM_SML);

    const int TB = 256;
    const int nbN = (NNODES + TB - 1) / TB;
    const int nbE = (NEDGES + TB - 1) / TB;
    const int nbM = (NNODES + 127) / 128;        // GEMM blocks (128 rows)
    const int nbA = (NNODES + 7) / 8;            // agg blocks (8 warps/block)

    // Launch order arranged so the layer-0 GEMM is launch index 3 (the one
    // ncu's -s/-c window captures), while preserving dependencies.
    k_prepW<FIN, HID><<<(FIN * HID + TB - 1) / TB, TB>>>(W0, w0h, w0l);     // 0
    k_zero_init<<<nbN, TB>>>();                                              // 1
    k_count<<<nbE, TB>>>(ei);                                                // 2
    k_tgemm512<FIN, HID, true><<<nbM, 512, SM_BIG>>>(x, nullptr, nullptr,
                                                     w0h, w0l, tmp);         // 3
    k_dinv<<<nbN, TB>>>();
    k_scan1<<<SCAN_NB, SCAN_TPB>>>();
    k_scan2<<<1, 64>>>();
    k_scan3<<<SCAN_NB, SCAN_TPB>>>();
    k_fill<<<nbE, TB>>>(ei);
    k_prepW<HID, HID><<<(HID * HID + TB - 1) / TB, TB>>>(W1, w1h, w1l);
    k_prepW<HID, HID><<<(HID * HID + TB - 1) / TB, TB>>>(W2, w2h, w2l);
    k_prepW<HID, COUT><<<(HID * COUT + TB - 1) / TB, TB>>>(W3, w3h, w3l);

    // layer 0 aggregation -> relu'd split h0
    k_agg128s<false><<<nbA, TB>>>(tmp, ah, al, ph, pl);
    // layer 1
    k_tgemm512<HID, HID, false><<<nbM, 512, SM_BIG>>>(nullptr, ah, al, w1h, w1l, tmp);
    k_agg128s<false><<<nbA, TB>>>(tmp, ah, al, ph, pl);
    // layer 2 (pre-relu h2 kept for corr_2)
    k_tgemm512<HID, HID, false><<<nbM, 512, SM_BIG>>>(nullptr, ah, al, w2h, w2l, tmp);
    k_agg128s<true><<<nbA, TB>>>(tmp, ah, al, ph, pl);

    // corr_2 metric on h2 (pre-relu split)
    k_zero_G<<<(HID * HID + TB - 1) / TB, TB>>>();
    k_gram_split<<<296, 256>>>(ph, pl);
    k_finalize<HID><<<1, 256>>>(out + NNODES * COUT);

    // layer 3: relu(h2) @ W3 -> agg directly into d_out
    k_tgemm512<HID, COUT, false><<<nbM, 512, SM_SML>>>(nullptr, ah, al, w3h, w3l, tmp);
    k_agg64h<<<nbA, TB>>>(tmp, out);

    // corr metric on h3
    k_zero_G<<<(HID * HID + TB - 1) / TB, TB>>>();
    k_gram_mma<COUT><<<296, 256>>>(out);
    k_finalize<COUT><<<1, 256>>>(out + NNODES * COUT + 1);
}

// round 7
// speedup vs baseline: 1.0609x; 1.0609x over previous
#include <cuda_runtime.h>
#include <cuda_bf16.h>
#include <cuda_fp16.h>
#include <math.h>
#include <stdint.h>

#define NNODES 100000
#define NEDGES 1600000
#define FIN 256
#define HID 128
#define COUT 64

#define SCAN_TPB 256
#define SCAN_ELEMS 8
#define SCAN_CHUNK (SCAN_TPB * SCAN_ELEMS)                 // 2048
#define SCAN_NB ((NNODES + SCAN_CHUNK - 1) / SCAN_CHUNK)   // 49

// ---------------- scratch (static __device__, no allocation) ----------------
__device__ __half g_tmp[NNODES * HID];          // GEMM output (messages), fp16
__device__ __nv_bfloat16 g_ah[NNODES * HID];    // relu'd h, hi split (GEMM input)
__device__ __nv_bfloat16 g_al[NNODES * HID];    // relu'd h, lo split
__device__ __nv_bfloat16 g_ph[NNODES * HID];    // pre-relu h2, hi split (gram)
__device__ __nv_bfloat16 g_pl[NNODES * HID];    // pre-relu h2, lo split
__device__ float g_dinv[NNODES];
__device__ int   g_cnt[NNODES];
__device__ int   g_cursor[NNODES];
__device__ int   g_rowptr[NNODES + 1];
__device__ int   g_col[NEDGES];
__device__ float g_w[NEDGES];
__device__ float g_G[HID * HID];
__device__ float g_csum[HID];
__device__ int   g_bsum[SCAN_NB];

// split-bf16 transposed weights: Wt[d][k] = W[k][d]
__device__ __nv_bfloat16 g_w0h[HID * FIN],  g_w0l[HID * FIN];
__device__ __nv_bfloat16 g_w1h[HID * HID],  g_w1l[HID * HID];
__device__ __nv_bfloat16 g_w2h[HID * HID],  g_w2l[HID * HID];
__device__ __nv_bfloat16 g_w3h[COUT * HID], g_w3l[COUT * HID];

// ---------------- helpers ----------------
__device__ __forceinline__ uint32_t smem_u32(const void* p) {
    uint32_t a;
    asm("{ .reg .u64 t; cvta.to.shared.u64 t, %1; cvt.u32.u64 %0, t; }"
        : "=r"(a) : "l"(p));
    return a;
}
__device__ __forceinline__ uint32_t sw128(uint32_t off) {
    return off ^ ((off >> 3) & 0x70);
}
__device__ __forceinline__ void ldsm4(uint32_t* r, uint32_t addr) {
    asm volatile("ldmatrix.sync.aligned.m8n8.x4.shared.b16 {%0,%1,%2,%3}, [%4];"
                 : "=r"(r[0]), "=r"(r[1]), "=r"(r[2]), "=r"(r[3]) : "r"(addr));
}
__device__ __forceinline__ void mma16816(float* c, const uint32_t* a,
                                         const uint32_t* b) {
    asm volatile(
        "mma.sync.aligned.m16n8k16.row.col.f32.bf16.bf16.f32 "
        "{%0,%1,%2,%3}, {%4,%5,%6,%7}, {%8,%9}, {%0,%1,%2,%3};"
        : "+f"(c[0]), "+f"(c[1]), "+f"(c[2]), "+f"(c[3])
        : "r"(a[0]), "r"(a[1]), "r"(a[2]), "r"(a[3]), "r"(b[0]), "r"(b[1]));
}
__device__ __forceinline__ void split2(float f, __nv_bfloat16& h, __nv_bfloat16& l) {
    h = __float2bfloat16_rn(f);
    l = __float2bfloat16_rn(f - __bfloat162float(h));
}
__device__ __forceinline__ void cpa16(uint32_t dst, const void* src, int nbytes) {
    asm volatile("cp.async.cg.shared.global [%0], [%1], 16, %2;"
                 :: "r"(dst), "l"(src), "r"(nbytes) : "memory");
}
__device__ __forceinline__ void cpa_commit() {
    asm volatile("cp.async.commit_group;" ::: "memory");
}
__device__ __forceinline__ void cpa_wait1() {
    asm volatile("cp.async.wait_group 1;" ::: "memory");
}
__device__ __forceinline__ void cpa_wait0() {
    asm volatile("cp.async.wait_group 0;" ::: "memory");
}

// ---------------- preprocessing ----------------
__global__ void k_zero_init() {
    int i = blockIdx.x * blockDim.x + threadIdx.x;
    if (i < NNODES) { g_cnt[i] = 0; g_cursor[i] = 0; }
}

__global__ void k_zero_G() {
    int i = blockIdx.x * blockDim.x + threadIdx.x;
    if (i < HID * HID) g_G[i] = 0.f;
    if (i < HID) g_csum[i] = 0.f;
}

__global__ void k_count(const int* __restrict__ ei) {
    int e = blockIdx.x * blockDim.x + threadIdx.x;
    if (e < NEDGES) atomicAdd(&g_cnt[ei[e]], 1);
}

// scan pass 1 (also computes dinv: reads g_cnt anyway)
__global__ void k_scan1() {
    __shared__ int warp_s[SCAN_TPB / 32];
    int tid = threadIdx.x, blk = blockIdx.x;
    int base = blk * SCAN_CHUNK + tid * SCAN_ELEMS;
    int s = 0;
#pragma unroll
    for (int i = 0; i < SCAN_ELEMS; i++) {
        int idx = base + i;
        if (idx < NNODES) {
            int c = g_cnt[idx];
            s += c;
            g_dinv[idx] = rsqrtf((float)(c + 1));  // +1 self loop
        }
    }
    for (int o = 16; o > 0; o >>= 1) s += __shfl_down_sync(0xffffffffu, s, o);
    if ((tid & 31) == 0) warp_s[tid >> 5] = s;
    __syncthreads();
    if (tid < SCAN_TPB / 32) {
        int w = warp_s[tid];
        for (int o = (SCAN_TPB / 64); o > 0; o >>= 1)
            w += __shfl_down_sync(0xffu, w, o);
        if (tid == 0) g_bsum[blk] = w;
    }
}

__global__ void k_scan2() {
    __shared__ int sh[64];
    int tid = threadIdx.x;
    sh[tid] = (tid < SCAN_NB) ? g_bsum[tid] : 0;
    __syncthreads();
    for (int o = 1; o < 64; o <<= 1) {
        int v = (tid >= o) ? sh[tid - o] : 0;
        __syncthreads();
        sh[tid] += v;
        __syncthreads();
    }
    if (tid < SCAN_NB) g_bsum[tid] = (tid == 0) ? 0 : sh[tid - 1];
    if (tid == 0) g_rowptr[NNODES] = sh[SCAN_NB - 1];
}

__global__ void k_scan3() {
    __shared__ int tsum[SCAN_TPB];
    int tid = threadIdx.x, blk = blockIdx.x;
    int base = blk * SCAN_CHUNK + tid * SCAN_ELEMS;
    int c[SCAN_ELEMS];
    int s = 0;
#pragma unroll
    for (int i = 0; i < SCAN_ELEMS; i++) {
        int idx = base + i;
        c[i] = (idx < NNODES) ? g_cnt[idx] : 0;
        s += c[i];
    }
    tsum[tid] = s;
    __syncthreads();
    for (int o = 1; o < SCAN_TPB; o <<= 1) {
        int v = (tid >= o) ? tsum[tid - o] : 0;
        __syncthreads();
        tsum[tid] += v;
        __syncthreads();
    }
    int run = g_bsum[blk] + ((tid == 0) ? 0 : tsum[tid - 1]);
#pragma unroll
    for (int i = 0; i < SCAN_ELEMS; i++) {
        int idx = base + i;
        if (idx < NNODES) { g_rowptr[idx] = run; run += c[i]; }
    }
}

__global__ void k_fill(const int* __restrict__ ei) {
    int e = blockIdx.x * blockDim.x + threadIdx.x;
    if (e >= NEDGES) return;
    int r = ei[e];
    int c = ei[NEDGES + e];
    int pos = g_rowptr[r] + atomicAdd(&g_cursor[r], 1);
    g_col[pos] = c;
    g_w[pos] = g_dinv[r] * g_dinv[c];
}

// ---------------- weight prep: W[K,D] fp32 -> Wt hi/lo bf16 [D][K] ----------
template <int K, int D>
__global__ void k_prepW(const float* __restrict__ W,
                        __nv_bfloat16* __restrict__ Wh,
                        __nv_bfloat16* __restrict__ Wl) {
    int i = blockIdx.x * blockDim.x + threadIdx.x;
    if (i >= K * D) return;
    int n = i / K, k = i % K;
    float v = W[k * D + n];
    __nv_bfloat16 h, l;
    split2(v, h, l);
    Wh[n * K + k] = h;
    Wl[n * K + k] = l;
}

// ---------------- pipelined tensor-core split-bf16 GEMM --------------------
// C[N,D] = A[N,K] @ W[K,D]. 512 threads (16 warps, 4x4). CTA tile 128 x D.
// 2-stage ping-pong smem; cp.async for B (+A when pre-split); for CONVERT
// (fp32 A, layer 0) global loads of chunk ch+1 are issued before the MMA of
// chunk ch and converted/stored after it.
template <int K, int D, bool CONVERT>
__global__ __launch_bounds__(512) void k_tgemm512(const float* __restrict__ Af,
                                                  const __nv_bfloat16* __restrict__ Ah,
                                                  const __nv_bfloat16* __restrict__ Al,
                                                  const __nv_bfloat16* __restrict__ Bh,
                                                  const __nv_bfloat16* __restrict__ Bl,
                                                  __half* __restrict__ C) {
    extern __shared__ __align__(1024) uint8_t smem[];
    const int CK = 64;                   // K elems per chunk
    const int NCH = K / CK;
    const int WN = D / 4;                // 32 (D=128) or 16 (D=64)
    const int NT = WN / 8;               // 4 or 2
    const int STA = 128 * 128;           // 16KB per A buffer
    const int SBB = D * 128;             // B buffer bytes
    const int OFF_B = 4 * STA;

    uint32_t sb = smem_u32(smem);
    int tid = threadIdx.x, wid = tid >> 5, lane = tid & 31;
    int wm = wid & 3, wn = wid >> 2;
    int row0 = wm * 32;
    int col0 = wn * WN;
    int grow = blockIdx.x * 128;

    float acc[2][NT][4];
#pragma unroll
    for (int i = 0; i < 2; i++)
#pragma unroll
        for (int j = 0; j < NT; j++)
#pragma unroll
            for (int q = 0; q < 4; q++) acc[i][j][q] = 0.f;

    float4 pf[4];                        // CONVERT prefetch registers

    // ---- load issue helpers (inlined lambdas) ----
    auto a_async = [&](int s, int ch) {
        int kk = ch * CK;
#pragma unroll
        for (int i = 0; i < 2; i++) {
            int u = tid + i * 512;
            int m = u >> 3, g = u & 7;
            int r = grow + m;
            int rc = (r < NNODES) ? r : 0;
            int nb = (r < NNODES) ? 16 : 0;
            uint32_t so = sw128((uint32_t)(m * 128 + g * 16));
            cpa16(sb + (2 * s) * STA + so, &Ah[(size_t)rc * K + kk + g * 8], nb);
            cpa16(sb + (2 * s + 1) * STA + so, &Al[(size_t)rc * K + kk + g * 8], nb);
        }
    };
    auto b_async = [&](int s, int ch) {
        int kk = ch * CK;
#pragma unroll
        for (int i = 0; i < (D * 8 + 511) / 512; i++) {
            int u = tid + i * 512;
            if (u < D * 8) {
                int n = u >> 3, g = u & 7;
                uint32_t so = sw128((uint32_t)(n * 128 + g * 16));
                cpa16(sb + OFF_B + (2 * s) * SBB + so, &Bh[n * K + kk + g * 8], 16);
                cpa16(sb + OFF_B + (2 * s + 1) * SBB + so, &Bl[n * K + kk + g * 8], 16);
            }
        }
    };
    auto a_ldregs = [&](int ch) {
        int kk = ch * CK;
#pragma unroll
        for (int i = 0; i < 2; i++) {
            int u = tid + i * 512;
            int m = u >> 3, g = u & 7;
            int r = grow + m;
            pf[2 * i] = make_float4(0.f, 0.f, 0.f, 0.f);
            pf[2 * i + 1] = pf[2 * i];
            if (r < NNODES) {
                const float* p = &Af[(size_t)r * K + kk + g * 8];
                pf[2 * i] = *(const float4*)p;
                pf[2 * i + 1] = *(const float4*)(p + 4);
            }
        }
    };
    auto a_cvtsts = [&](int s) {
#pragma unroll
        for (int i = 0; i < 2; i++) {
            int u = tid + i * 512;
            int m = u >> 3, g = u & 7;
            float f[8] = {pf[2 * i].x, pf[2 * i].y, pf[2 * i].z, pf[2 * i].w,
                          pf[2 * i + 1].x, pf[2 * i + 1].y, pf[2 * i + 1].z, pf[2 * i + 1].w};
            uint32_t hp[4], lp[4];
#pragma unroll
            for (int j = 0; j < 4; j++) {
                __nv_bfloat16 h0, l0, h1, l1;
                split2(f[2 * j], h0, l0);
                split2(f[2 * j + 1], h1, l1);
                hp[j] = (uint32_t)__bfloat16_as_ushort(h0)
                      | ((uint32_t)__bfloat16_as_ushort(h1) << 16);
                lp[j] = (uint32_t)__bfloat16_as_ushort(l0)
                      | ((uint32_t)__bfloat16_as_ushort(l1) << 16);
            }
            uint32_t so = sw128((uint32_t)(m * 128 + g * 16));
            *(uint4*)(smem + (2 * s) * STA + so) = make_uint4(hp[0], hp[1], hp[2], hp[3]);
            *(uint4*)(smem + (2 * s + 1) * STA + so) = make_uint4(lp[0], lp[1], lp[2], lp[3]);
        }
    };

    // ---- prologue: fill stage 0 ----
    if (CONVERT) { a_ldregs(0); a_cvtsts(0); }
    else a_async(0, 0);
    b_async(0, 0);
    cpa_commit();

    // ---- pipelined main loop ----
    for (int ch = 0; ch < NCH; ch++) {
        int cur = ch & 1, nxt = cur ^ 1;
        bool more = (ch + 1 < NCH);
        if (more) {
            if (CONVERT) a_ldregs(ch + 1);     // LDGs in flight during MMA
            else a_async(nxt, ch + 1);
            b_async(nxt, ch + 1);
            cpa_commit();
        }
        if (more) cpa_wait1(); else cpa_wait0();
        __syncthreads();
        // ---- MMA on stage cur ----
        {
            uint32_t aB0 = sb + (2 * cur) * STA;
            uint32_t aB1 = sb + (2 * cur + 1) * STA;
            uint32_t bB0 = sb + OFF_B + (2 * cur) * SBB;
            uint32_t bB1 = sb + OFF_B + (2 * cur + 1) * SBB;
#pragma unroll
            for (int k16 = 0; k16 < CK / 16; k16++) {
                int kb = k16 * 32;
                uint32_t ah[2][4], al[2][4];
#pragma unroll
                for (int mt = 0; mt < 2; mt++) {
                    int r = row0 + mt * 16 + (lane & 15);
                    int cb = kb + ((lane & 16) ? 16 : 0);
                    uint32_t so = sw128((uint32_t)(r * 128 + cb));
                    ldsm4(ah[mt], aB0 + so);
                    ldsm4(al[mt], aB1 + so);
                }
#pragma unroll
                for (int bt = 0; bt < NT / 2; bt++) {
                    int n = col0 + bt * 16 + (lane & 7) + ((lane & 16) ? 8 : 0);
                    int cb = kb + ((lane & 8) ? 16 : 0);
                    uint32_t so = sw128((uint32_t)(n * 128 + cb));
                    uint32_t bh[4], bl[4];
                    ldsm4(bh, bB0 + so);
                    ldsm4(bl, bB1 + so);
#pragma unroll
                    for (int h = 0; h < 2; h++) {
                        int nt = bt * 2 + h;
#pragma unroll
                        for (int mt = 0; mt < 2; mt++) {
                            mma16816(acc[mt][nt], ah[mt], &bh[h * 2]);
                            mma16816(acc[mt][nt], ah[mt], &bl[h * 2]);
                            mma16816(acc[mt][nt], al[mt], &bh[h * 2]);
                        }
                    }
                }
            }
        }
        if (more && CONVERT) a_cvtsts(nxt);    // STS after MMA (LDG latency hidden)
        __syncthreads();                       // stage cur free for ch+2 writes
    }

    // ---- epilogue: fragment -> global fp16 (half2 per store)
#pragma unroll
    for (int mt = 0; mt < 2; mt++) {
        int r0 = grow + row0 + mt * 16 + (lane >> 2);
        int r1 = r0 + 8;
#pragma unroll
        for (int nt = 0; nt < NT; nt++) {
            int cc = col0 + nt * 8 + (lane & 3) * 2;
            if (r0 < NNODES)
                *(__half2*)&C[(size_t)r0 * D + cc] =
                    __floats2half2_rn(acc[mt][nt][0], acc[mt][nt][1]);
            if (r1 < NNODES)
                *(__half2*)&C[(size_t)r1 * D + cc] =
                    __floats2half2_rn(acc[mt][nt][2], acc[mt][nt][3]);
        }
    }
}

// ---------------- sparse aggregation (fp16 gather, fp32 accumulate) --------
// h[i] = dinv[i]^2 * tmp[i] + sum_e w_e * tmp[col_e]; writes relu(h) as
// split bf16 (GEMM operand); PRE also stores pre-relu split (gram operand).
template <bool PRE>
__global__ void k_agg128s(const __half* __restrict__ tmp,
                          __nv_bfloat16* __restrict__ ah,
                          __nv_bfloat16* __restrict__ al,
                          __nv_bfloat16* __restrict__ ph,
                          __nv_bfloat16* __restrict__ pl) {
    int gw = (blockIdx.x * blockDim.x + threadIdx.x) >> 5;
    int lane = threadIdx.x & 31;
    if (gw >= NNODES) return;
    const uint2* __restrict__ t = (const uint2*)tmp;   // 4 halves per lane
    float di = g_dinv[gw];
    float s = di * di;
    uint2 u = t[gw * 32 + lane];
    float2 p0 = __half22float2(*(__half2*)&u.x);
    float2 p1 = __half22float2(*(__half2*)&u.y);
    float4 acc = make_float4(p0.x * s, p0.y * s, p1.x * s, p1.y * s);
    float4 acc2 = make_float4(0.f, 0.f, 0.f, 0.f);
    int e = g_rowptr[gw], en = g_rowptr[gw + 1];
    // 4-way unrolled (MLP=4 against L2 latency)
    for (; e + 3 < en; e += 4) {
        int c0 = g_col[e], c1 = g_col[e + 1], c2 = g_col[e + 2], c3 = g_col[e + 3];
        float w0 = g_w[e], w1 = g_w[e + 1], w2 = g_w[e + 2], w3 = g_w[e + 3];
        uint2 a = t[c0 * 32 + lane];
        uint2 b = t[c1 * 32 + lane];
        uint2 cc = t[c2 * 32 + lane];
        uint2 d = t[c3 * 32 + lane];
        float2 a0 = __half22float2(*(__half2*)&a.x), a1 = __half22float2(*(__half2*)&a.y);
        float2 b0 = __half22float2(*(__half2*)&b.x), b1 = __half22float2(*(__half2*)&b.y);
        float2 c0f = __half22float2(*(__half2*)&cc.x), c1f = __half22float2(*(__half2*)&cc.y);
        float2 d0 = __half22float2(*(__half2*)&d.x), d1 = __half22float2(*(__half2*)&d.y);
        acc.x = fmaf(w0, a0.x, acc.x);   acc.y = fmaf(w0, a0.y, acc.y);
        acc.z = fmaf(w0, a1.x, acc.z);   acc.w = fmaf(w0, a1.y, acc.w);
        acc2.x = fmaf(w1, b0.x, acc2.x); acc2.y = fmaf(w1, b0.y, acc2.y);
        acc2.z = fmaf(w1, b1.x, acc2.z); acc2.w = fmaf(w1, b1.y, acc2.w);
        acc.x = fmaf(w2, c0f.x, acc.x);  acc.y = fmaf(w2, c0f.y, acc.y);
        acc.z = fmaf(w2, c1f.x, acc.z);  acc.w = fmaf(w2, c1f.y, acc.w);
        acc2.x = fmaf(w3, d0.x, acc2.x); acc2.y = fmaf(w3, d0.y, acc2.y);
        acc2.z = fmaf(w3, d1.x, acc2.z); acc2.w = fmaf(w3, d1.y, acc2.w);
    }
    for (; e < en; e++) {
        int c0 = g_col[e];
        float w0 = g_w[e];
        uint2 a = t[c0 * 32 + lane];
        float2 a0 = __half22float2(*(__half2*)&a.x);
        float2 a1 = __half22float2(*(__half2*)&a.y);
        acc.x = fmaf(w0, a0.x, acc.x); acc.y = fmaf(w0, a0.y, acc.y);
        acc.z = fmaf(w0, a1.x, acc.z); acc.w = fmaf(w0, a1.y, acc.w);
    }
    acc.x += acc2.x; acc.y += acc2.y; acc.z += acc2.z; acc.w += acc2.w;

    float f[4] = {acc.x, acc.y, acc.z, acc.w};
    size_t base = (size_t)gw * HID + lane * 4;
    if (PRE) {
        ushort hh[4], ll[4];
#pragma unroll
        for (int j = 0; j < 4; j++) {
            __nv_bfloat16 h, l;
            split2(f[j], h, l);
            hh[j] = __bfloat16_as_ushort(h);
            ll[j] = __bfloat16_as_ushort(l);
        }
        *(uint2*)&ph[base] = make_uint2((uint32_t)hh[0] | ((uint32_t)hh[1] << 16),
                                        (uint32_t)hh[2] | ((uint32_t)hh[3] << 16));
        *(uint2*)&pl[base] = make_uint2((uint32_t)ll[0] | ((uint32_t)ll[1] << 16),
                                        (uint32_t)ll[2] | ((uint32_t)ll[3] << 16));
    }
    ushort rh[4], rl[4];
#pragma unroll
    for (int j = 0; j < 4; j++) {
        float v = fmaxf(f[j], 0.f);
        __nv_bfloat16 h, l;
        split2(v, h, l);
        rh[j] = __bfloat16_as_ushort(h);
        rl[j] = __bfloat16_as_ushort(l);
    }
    *(uint2*)&ah[base] = make_uint2((uint32_t)rh[0] | ((uint32_t)rh[1] << 16),
                                    (uint32_t)rh[2] | ((uint32_t)rh[3] << 16));
    *(uint2*)&al[base] = make_uint2((uint32_t)rl[0] | ((uint32_t)rl[1] << 16),
                                    (uint32_t)rl[2] | ((uint32_t)rl[3] << 16));
}

__global__ void k_agg64h(const __half* __restrict__ tmp, float* __restrict__ out) {
    int gw = (blockIdx.x * blockDim.x + threadIdx.x) >> 5;
    int lane = threadIdx.x & 31;
    if (gw >= NNODES) return;
    const uint32_t* __restrict__ t = (const uint32_t*)tmp;  // 2 halves per lane
    float di = g_dinv[gw];
    float s = di * di;
    uint32_t u = t[gw * 32 + lane];
    float2 p = __half22float2(*(__half2*)&u);
    float2 acc = make_float2(p.x * s, p.y * s);
    float2 acc2 = make_float2(0.f, 0.f);
    int e = g_rowptr[gw], en = g_rowptr[gw + 1];
    for (; e + 3 < en; e += 4) {
        int c0 = g_col[e], c1 = g_col[e + 1], c2 = g_col[e + 2], c3 = g_col[e + 3];
        float w0 = g_w[e], w1 = g_w[e + 1], w2 = g_w[e + 2], w3 = g_w[e + 3];
        uint32_t a = t[c0 * 32 + lane];
        uint32_t b = t[c1 * 32 + lane];
        uint32_t c = t[c2 * 32 + lane];
        uint32_t d = t[c3 * 32 + lane];
        float2 af = __half22float2(*(__half2*)&a);
        float2 bf = __half22float2(*(__half2*)&b);
        float2 cf = __half22float2(*(__half2*)&c);
        float2 df = __half22float2(*(__half2*)&d);
        acc.x = fmaf(w0, af.x, acc.x);   acc.y = fmaf(w0, af.y, acc.y);
        acc2.x = fmaf(w1, bf.x, acc2.x); acc2.y = fmaf(w1, bf.y, acc2.y);
        acc.x = fmaf(w2, cf.x, acc.x);   acc.y = fmaf(w2, cf.y, acc.y);
        acc2.x = fmaf(w3, df.x, acc2.x); acc2.y = fmaf(w3, df.y, acc2.y);
    }
    for (; e < en; e++) {
        int c0 = g_col[e];
        float w0 = g_w[e];
        uint32_t a = t[c0 * 32 + lane];
        float2 af = __half22float2(*(__half2*)&a);
        acc.x = fmaf(w0, af.x, acc.x); acc.y = fmaf(w0, af.y, acc.y);
    }
    acc.x += acc2.x; acc.y += acc2.y;
    ((float2*)out)[gw * 32 + lane] = acc;
}

// ---------------- Gram via mma from pre-split bf16 h2 (D=128) ---------------
__global__ __launch_bounds__(256) void k_gram_split(const __nv_bfloat16* __restrict__ ph,
                                                    const __nv_bfloat16* __restrict__ pl) {
    const int D = HID;
    __shared__ __align__(1024) uint8_t sm[2 * D * 128];
    const int OFF_L = D * 128;
    const int FG = D / 4;
    const int PAIRS = 256 / FG;
    const int NT = D / 8;
    const int MW = D / 16;
    uint32_t sb = smem_u32(sm);
    int tid = threadIdx.x, wid = tid >> 5, lane = tid & 31;
    int f4 = tid % FG;
    int rp0 = tid / FG;

    float acc[NT][4];
#pragma unroll
    for (int j = 0; j < NT; j++)
#pragma unroll
        for (int q = 0; q < 4; q++) acc[j][q] = 0.f;
    float cs0 = 0.f, cs1 = 0.f, cs2 = 0.f, cs3 = 0.f;

    const int NCHUNK = (NNODES + 63) / 64;
    for (int ch = blockIdx.x; ch < NCHUNK; ch += gridDim.x) {
        int rbase = ch * 64;
#pragma unroll
        for (int it = 0; it < 32 / PAIRS; it++) {
            int pr = rp0 + it * PAIRS;
            int r0 = rbase + pr * 2, r1 = r0 + 1;
            uint2 h0v = make_uint2(0, 0), h1v = h0v, l0v = h0v, l1v = h0v;
            if (r0 < NNODES) {
                h0v = *(const uint2*)&ph[(size_t)r0 * D + f4 * 4];
                l0v = *(const uint2*)&pl[(size_t)r0 * D + f4 * 4];
            }
            if (r1 < NNODES) {
                h1v = *(const uint2*)&ph[(size_t)r1 * D + f4 * 4];
                l1v = *(const uint2*)&pl[(size_t)r1 * D + f4 * 4];
            }
            const ushort* h0s = (const ushort*)&h0v;
            const ushort* h1s = (const ushort*)&h1v;
            const ushort* l0s = (const ushort*)&l0v;
            const ushort* l1s = (const ushort*)&l1v;
            float fs[4];
#pragma unroll
            for (int j = 0; j < 4; j++) {
                fs[j] = __bfloat162float(__ushort_as_bfloat16(h0s[j]))
                      + __bfloat162float(__ushort_as_bfloat16(l0s[j]))
                      + __bfloat162float(__ushort_as_bfloat16(h1s[j]))
                      + __bfloat162float(__ushort_as_bfloat16(l1s[j]));
                int feat = f4 * 4 + j;
                uint32_t hp = (uint32_t)h0s[j] | ((uint32_t)h1s[j] << 16);
                uint32_t lp = (uint32_t)l0s[j] | ((uint32_t)l1s[j] << 16);
                uint32_t so = sw128((uint32_t)(feat * 128 + pr * 4));
                *(uint32_t*)(sm + so) = hp;
                *(uint32_t*)(sm + OFF_L + so) = lp;
            }
            cs0 += fs[0]; cs1 += fs[1]; cs2 += fs[2]; cs3 += fs[3];
        }
        __syncthreads();
        if (wid < MW) {
#pragma unroll
            for (int k16 = 0; k16 < 4; k16++) {
                int kb = k16 * 32;
                uint32_t ah[4], al[4];
                {
                    int r = wid * 16 + (lane & 15);
                    int cb = kb + ((lane & 16) ? 16 : 0);
                    uint32_t so = sw128((uint32_t)(r * 128 + cb));
                    ldsm4(ah, sb + so);
                    ldsm4(al, sb + OFF_L + so);
                }
#pragma unroll
                for (int bt = 0; bt < NT / 2; bt++) {
                    int n = bt * 16 + (lane & 7) + ((lane & 16) ? 8 : 0);
                    int cb = kb + ((lane & 8) ? 16 : 0);
                    uint32_t so = sw128((uint32_t)(n * 128 + cb));
                    uint32_t bh[4], bl[4];
                    ldsm4(bh, sb + so);
                    ldsm4(bl, sb + OFF_L + so);
#pragma unroll
                    for (int hh = 0; hh < 2; hh++) {
                        int nt = bt * 2 + hh;
                        mma16816(acc[nt], ah, &bh[hh * 2]);
                        mma16816(acc[nt], ah, &bl[hh * 2]);
                        mma16816(acc[nt], al, &bh[hh * 2]);
                    }
                }
            }
        }
        __syncthreads();
    }
    if (wid < MW) {
        int mrow = wid * 16 + (lane >> 2);
#pragma unroll
        for (int nt = 0; nt < NT; nt++) {
            int c = nt * 8 + (lane & 3) * 2;
            atomicAdd(&g_G[mrow * D + c], acc[nt][0]);
            atomicAdd(&g_G[mrow * D + c + 1], acc[nt][1]);
            atomicAdd(&g_G[(mrow + 8) * D + c], acc[nt][2]);
            atomicAdd(&g_G[(mrow + 8) * D + c + 1], acc[nt][3]);
        }
    }
    atomicAdd(&g_csum[f4 * 4 + 0], cs0);
    atomicAdd(&g_csum[f4 * 4 + 1], cs1);
    atomicAdd(&g_csum[f4 * 4 + 2], cs2);
    atomicAdd(&g_csum[f4 * 4 + 3], cs3);
}

// ---------------- Gram via mma from fp32 (D=64, for h3/out) -----------------
template <int D>
__global__ __launch_bounds__(256) void k_gram_mma(const float* __restrict__ h) {
    __shared__ __align__(1024) uint8_t sm[2 * D * 128];
    const int OFF_L = D * 128;
    const int FG = D / 4;
    const int PAIRS = 256 / FG;
    const int NT = D / 8;
    const int MW = D / 16;
    uint32_t sb = smem_u32(sm);
    int tid = threadIdx.x, wid = tid >> 5, lane = tid & 31;
    int f4 = tid % FG;
    int rp0 = tid / FG;

    float acc[NT][4];
#pragma unroll
    for (int j = 0; j < NT; j++)
#pragma unroll
        for (int q = 0; q < 4; q++) acc[j][q] = 0.f;
    float cs0 = 0.f, cs1 = 0.f, cs2 = 0.f, cs3 = 0.f;

    const int NCHUNK = (NNODES + 63) / 64;
    for (int ch = blockIdx.x; ch < NCHUNK; ch += gridDim.x) {
        int rbase = ch * 64;
#pragma unroll
        for (int it = 0; it < 32 / PAIRS; it++) {
            int pr = rp0 + it * PAIRS;
            int r0 = rbase + pr * 2, r1 = r0 + 1;
            float4 v0 = make_float4(0.f, 0.f, 0.f, 0.f), v1 = v0;
            if (r0 < NNODES) v0 = *(const float4*)&h[(size_t)r0 * D + f4 * 4];
            if (r1 < NNODES) v1 = *(const float4*)&h[(size_t)r1 * D + f4 * 4];
            cs0 += v0.x + v1.x; cs1 += v0.y + v1.y;
            cs2 += v0.z + v1.z; cs3 += v0.w + v1.w;
            float a0[4] = {v0.x, v0.y, v0.z, v0.w};
            float a1[4] = {v1.x, v1.y, v1.z, v1.w};
#pragma unroll
            for (int j = 0; j < 4; j++) {
                int feat = f4 * 4 + j;
                __nv_bfloat16 h0, l0, h1, l1;
                split2(a0[j], h0, l0);
                split2(a1[j], h1, l1);
                uint32_t hp = (uint32_t)__bfloat16_as_ushort(h0)
                            | ((uint32_t)__bfloat16_as_ushort(h1) << 16);
                uint32_t lp = (uint32_t)__bfloat16_as_ushort(l0)
                            | ((uint32_t)__bfloat16_as_ushort(l1) << 16);
                uint32_t so = sw128((uint32_t)(feat * 128 + pr * 4));
                *(uint32_t*)(sm + so) = hp;
                *(uint32_t*)(sm + OFF_L + so) = lp;
            }
        }
        __syncthreads();
        if (wid < MW) {
#pragma unroll
            for (int k16 = 0; k16 < 4; k16++) {
                int kb = k16 * 32;
                uint32_t ah[4], al[4];
                {
                    int r = wid * 16 + (lane & 15);
                    int cb = kb + ((lane & 16) ? 16 : 0);
                    uint32_t so = sw128((uint32_t)(r * 128 + cb));
                    ldsm4(ah, sb + so);
                    ldsm4(al, sb + OFF_L + so);
                }
#pragma unroll
                for (int bt = 0; bt < NT / 2; bt++) {
                    int n = bt * 16 + (lane & 7) + ((lane & 16) ? 8 : 0);
                    int cb = kb + ((lane & 8) ? 16 : 0);
                    uint32_t so = sw128((uint32_t)(n * 128 + cb));
                    uint32_t bh[4], bl[4];
                    ldsm4(bh, sb + so);
                    ldsm4(bl, sb + OFF_L + so);
#pragma unroll
                    for (int hh = 0; hh < 2; hh++) {
                        int nt = bt * 2 + hh;
                        mma16816(acc[nt], ah, &bh[hh * 2]);
                        mma16816(acc[nt], ah, &bl[hh * 2]);
                        mma16816(acc[nt], al, &bh[hh * 2]);
                    }
                }
            }
        }
        __syncthreads();
    }
    if (wid < MW) {
        int mrow = wid * 16 + (lane >> 2);
#pragma unroll
        for (int nt = 0; nt < NT; nt++) {
            int c = nt * 8 + (lane & 3) * 2;
            atomicAdd(&g_G[mrow * D + c], acc[nt][0]);
            atomicAdd(&g_G[mrow * D + c + 1], acc[nt][1]);
            atomicAdd(&g_G[(mrow + 8) * D + c], acc[nt][2]);
            atomicAdd(&g_G[(mrow + 8) * D + c + 1], acc[nt][3]);
        }
    }
    atomicAdd(&g_csum[f4 * 4 + 0], cs0);
    atomicAdd(&g_csum[f4 * 4 + 1], cs1);
    atomicAdd(&g_csum[f4 * 4 + 2], cs2);
    atomicAdd(&g_csum[f4 * 4 + 3], cs3);
}

// ---------------- correlation metric finalize (single block) ----------------
template <int D>
__global__ void k_finalize(float* __restrict__ dst) {
    __shared__ float sd[D];
    __shared__ float red[256];
    int tid = threadIdx.x;
    const float invN = 1.0f / (float)NNODES;
    if (tid < D) {
        float cjj = g_G[tid * D + tid] - g_csum[tid] * g_csum[tid] * invN;
        sd[tid] = sqrtf(fmaxf(cjj, 1e-12f));
    }
    __syncthreads();
    float sum = 0.f;
    for (int idx = tid; idx < D * D; idx += 256) {
        int j = idx / D, k = idx % D;
        if (k > j) {
            float cov = g_G[idx] - g_csum[j] * g_csum[k] * invN;
            sum += fabsf(cov / (sd[j] * sd[k]));
        }
    }
    red[tid] = sum;
    __syncthreads();
    for (int off = 128; off > 0; off >>= 1) {
        if (tid < off) red[tid] += red[tid + off];
        __syncthreads();
    }
    if (tid == 0) *dst = red[0] / (float)(D * (D - 1) / 2);
}

// ---------------- launch ----------------
extern "C" void kernel_launch(void* const* d_in, const int* in_sizes, int n_in,
                              void* d_out, int out_size) {
    const float* x  = (const float*)d_in[0];
    const int*   ei = (const int*)d_in[1];
    const float* W0 = (const float*)d_in[2];
    const float* W1 = (const float*)d_in[3];
    const float* W2 = (const float*)d_in[4];
    const float* W3 = (const float*)d_in[5];
    float* out = (float*)d_out;

    __half* tmp;
    __nv_bfloat16 *ah, *al, *ph, *pl;
    cudaGetSymbolAddress((void**)&tmp, g_tmp);
    cudaGetSymbolAddress((void**)&ah, g_ah);
    cudaGetSymbolAddress((void**)&al, g_al);
    cudaGetSymbolAddress((void**)&ph, g_ph);
    cudaGetSymbolAddress((void**)&pl, g_pl);
    __nv_bfloat16 *w0h, *w0l, *w1h, *w1l, *w2h, *w2l, *w3h, *w3l;
    cudaGetSymbolAddress((void**)&w0h, g_w0h); cudaGetSymbolAddress((void**)&w0l, g_w0l);
    cudaGetSymbolAddress((void**)&w1h, g_w1h); cudaGetSymbolAddress((void**)&w1l, g_w1l);
    cudaGetSymbolAddress((void**)&w2h, g_w2h); cudaGetSymbolAddress((void**)&w2l, g_w2l);
    cudaGetSymbolAddress((void**)&w3h, g_w3h); cudaGetSymbolAddress((void**)&w3l, g_w3l);

    const int SM_BIG = 4 * 128 * 128 + 4 * HID * 128;   // 131072 (2 stages)
    const int SM_SML = 4 * 128 * 128 + 4 * COUT * 128;  // 98304
    cudaFuncSetAttribute(k_tgemm512<FIN, HID, true>,
                         cudaFuncAttributeMaxDynamicSharedMemorySize, SM_BIG);
    cudaFuncSetAttribute(k_tgemm512<HID, HID, false>,
                         cudaFuncAttributeMaxDynamicSharedMemorySize, SM_BIG);
    cudaFuncSetAttribute(k_tgemm512<HID, COUT, false>,
                         cudaFuncAttributeMaxDynamicSharedMemorySize, SM_SML);

    const int TB = 256;
    const int nbN = (NNODES + TB - 1) / TB;
    const int nbE = (NEDGES + TB - 1) / TB;
    const int nbM = (NNODES + 127) / 128;        // GEMM blocks (128 rows)
    const int nbA = (NNODES + 7) / 8;            // agg blocks (8 warps/block)

    // Launch order keeps the layer-0 GEMM at the ncu-captured launch index.
    k_prepW<FIN, HID><<<(FIN * HID + TB - 1) / TB, TB>>>(W0, w0h, w0l);     // 0
    k_zero_init<<<nbN, TB>>>();                                              // 1
    k_count<<<nbE, TB>>>(ei);                                                // 2
    k_tgemm512<FIN, HID, true><<<nbM, 512, SM_BIG>>>(x, nullptr, nullptr,
                                                     w0h, w0l, tmp);         // 3
    k_scan1<<<SCAN_NB, SCAN_TPB>>>();     // also computes dinv
    k_scan2<<<1, 64>>>();
    k_scan3<<<SCAN_NB, SCAN_TPB>>>();
    k_fill<<<nbE, TB>>>(ei);
    k_prepW<HID, HID><<<(HID * HID + TB - 1) / TB, TB>>>(W1, w1h, w1l);
    k_prepW<HID, HID><<<(HID * HID + TB - 1) / TB, TB>>>(W2, w2h, w2l);
    k_prepW<HID, COUT><<<(HID * COUT + TB - 1) / TB, TB>>>(W3, w3h, w3l);

    // layer 0 aggregation -> relu'd split h0
    k_agg128s<false><<<nbA, TB>>>(tmp, ah, al, ph, pl);
    // layer 1
    k_tgemm512<HID, HID, false><<<nbM, 512, SM_BIG>>>(nullptr, ah, al, w1h, w1l, tmp);
    k_agg128s<false><<<nbA, TB>>>(tmp, ah, al, ph, pl);
    // layer 2 (pre-relu h2 kept for corr_2)
    k_tgemm512<HID, HID, false><<<nbM, 512, SM_BIG>>>(nullptr, ah, al, w2h, w2l, tmp);
    k_agg128s<true><<<nbA, TB>>>(tmp, ah, al, ph, pl);

    // corr_2 metric on h2 (pre-relu split)
    k_zero_G<<<(HID * HID + TB - 1) / TB, TB>>>();
    k_gram_split<<<296, 256>>>(ph, pl);
    k_finalize<HID><<<1, 256>>>(out + NNODES * COUT);

    // layer 3: relu(h2) @ W3 -> agg directly into d_out
    k_tgemm512<HID, COUT, false><<<nbM, 512, SM_SML>>>(nullptr, ah, al, w3h, w3l, tmp);
    k_agg64h<<<nbA, TB>>>(tmp, out);

    // corr metric on h3
    k_zero_G<<<(HID * HID + TB - 1) / TB, TB>>>();
    k_gram_mma<COUT><<<296, 256>>>(out);
    k_finalize<COUT><<<1, 256>>>(out + NNODES * COUT + 1);
}

// round 8
// speedup vs baseline: 1.1236x; 1.0592x over previous
#include <cuda_runtime.h>
#include <cuda_bf16.h>
#include <cuda_fp16.h>
#include <math.h>
#include <stdint.h>

#define NNODES 100000
#define NEDGES 1600000
#define FIN 256
#define HID 128
#define COUT 64

#define SCAN_TPB 256
#define SCAN_ELEMS 8
#define SCAN_CHUNK (SCAN_TPB * SCAN_ELEMS)                 // 2048
#define SCAN_NB ((NNODES + SCAN_CHUNK - 1) / SCAN_CHUNK)   // 49

// ---------------- scratch (static __device__, no allocation) ----------------
__device__ __half g_tmp[NNODES * HID];          // GEMM output (messages), fp16
__device__ __nv_bfloat16 g_ah[NNODES * HID];    // relu'd h, hi split (GEMM input)
__device__ __nv_bfloat16 g_al[NNODES * HID];    // relu'd h, lo split
__device__ __nv_bfloat16 g_ph[NNODES * HID];    // pre-relu h2, hi split (gram)
__device__ __nv_bfloat16 g_pl[NNODES * HID];    // pre-relu h2, lo split
__device__ float g_dinv[NNODES];
__device__ int   g_cnt[NNODES];
__device__ int   g_cursor[NNODES];
__device__ int   g_rowptr[NNODES + 1];
__device__ int   g_col[NEDGES];
__device__ float g_w[NEDGES];
__device__ float g_G[HID * HID];
__device__ float g_csum[HID];
__device__ int   g_bsum[SCAN_NB];

// split-bf16 transposed weights: Wt[d][k] = W[k][d]
__device__ __nv_bfloat16 g_w0h[HID * FIN],  g_w0l[HID * FIN];
__device__ __nv_bfloat16 g_w1h[HID * HID],  g_w1l[HID * HID];
__device__ __nv_bfloat16 g_w2h[HID * HID],  g_w2l[HID * HID];
__device__ __nv_bfloat16 g_w3h[COUT * HID], g_w3l[COUT * HID];

// ---------------- helpers ----------------
__device__ __forceinline__ uint32_t smem_u32(const void* p) {
    uint32_t a;
    asm("{ .reg .u64 t; cvta.to.shared.u64 t, %1; cvt.u32.u64 %0, t; }"
        : "=r"(a) : "l"(p));
    return a;
}
__device__ __forceinline__ uint32_t sw128(uint32_t off) {
    return off ^ ((off >> 3) & 0x70);
}
__device__ __forceinline__ void ldsm4(uint32_t* r, uint32_t addr) {
    asm volatile("ldmatrix.sync.aligned.m8n8.x4.shared.b16 {%0,%1,%2,%3}, [%4];"
                 : "=r"(r[0]), "=r"(r[1]), "=r"(r[2]), "=r"(r[3]) : "r"(addr));
}
__device__ __forceinline__ void mma16816(float* c, const uint32_t* a,
                                         const uint32_t* b) {
    asm volatile(
        "mma.sync.aligned.m16n8k16.row.col.f32.bf16.bf16.f32 "
        "{%0,%1,%2,%3}, {%4,%5,%6,%7}, {%8,%9}, {%0,%1,%2,%3};"
        : "+f"(c[0]), "+f"(c[1]), "+f"(c[2]), "+f"(c[3])
        : "r"(a[0]), "r"(a[1]), "r"(a[2]), "r"(a[3]), "r"(b[0]), "r"(b[1]));
}
__device__ __forceinline__ void split2(float f, __nv_bfloat16& h, __nv_bfloat16& l) {
    h = __float2bfloat16_rn(f);
    l = __float2bfloat16_rn(f - __bfloat162float(h));
}
__device__ __forceinline__ void cpa16(uint32_t dst, const void* src, int nbytes) {
    asm volatile("cp.async.cg.shared.global [%0], [%1], 16, %2;"
                 :: "r"(dst), "l"(src), "r"(nbytes) : "memory");
}
__device__ __forceinline__ void cpa_commit() {
    asm volatile("cp.async.commit_group;" ::: "memory");
}
__device__ __forceinline__ void cpa_wait1() {
    asm volatile("cp.async.wait_group 1;" ::: "memory");
}
__device__ __forceinline__ void cpa_wait0() {
    asm volatile("cp.async.wait_group 0;" ::: "memory");
}

// ---------------- preprocessing ----------------
__global__ void k_zero_init() {
    int i = blockIdx.x * blockDim.x + threadIdx.x;
    if (i < NNODES) { g_cnt[i] = 0; g_cursor[i] = 0; }
}

__global__ void k_zero_G() {
    int i = blockIdx.x * blockDim.x + threadIdx.x;
    if (i < HID * HID) g_G[i] = 0.f;
    if (i < HID) g_csum[i] = 0.f;
}

__global__ void k_count(const int* __restrict__ ei) {
    int e = blockIdx.x * blockDim.x + threadIdx.x;
    if (e < NEDGES) atomicAdd(&g_cnt[ei[e]], 1);
}

// scan pass 1 (also computes dinv: reads g_cnt anyway)
__global__ void k_scan1() {
    __shared__ int warp_s[SCAN_TPB / 32];
    int tid = threadIdx.x, blk = blockIdx.x;
    int base = blk * SCAN_CHUNK + tid * SCAN_ELEMS;
    int s = 0;
#pragma unroll
    for (int i = 0; i < SCAN_ELEMS; i++) {
        int idx = base + i;
        if (idx < NNODES) {
            int c = g_cnt[idx];
            s += c;
            g_dinv[idx] = rsqrtf((float)(c + 1));  // +1 self loop
        }
    }
    for (int o = 16; o > 0; o >>= 1) s += __shfl_down_sync(0xffffffffu, s, o);
    if ((tid & 31) == 0) warp_s[tid >> 5] = s;
    __syncthreads();
    if (tid < SCAN_TPB / 32) {
        int w = warp_s[tid];
        for (int o = (SCAN_TPB / 64); o > 0; o >>= 1)
            w += __shfl_down_sync(0xffu, w, o);
        if (tid == 0) g_bsum[blk] = w;
    }
}

__global__ void k_scan2() {
    __shared__ int sh[64];
    int tid = threadIdx.x;
    sh[tid] = (tid < SCAN_NB) ? g_bsum[tid] : 0;
    __syncthreads();
    for (int o = 1; o < 64; o <<= 1) {
        int v = (tid >= o) ? sh[tid - o] : 0;
        __syncthreads();
        sh[tid] += v;
        __syncthreads();
    }
    if (tid < SCAN_NB) g_bsum[tid] = (tid == 0) ? 0 : sh[tid - 1];
    if (tid == 0) g_rowptr[NNODES] = sh[SCAN_NB - 1];
}

__global__ void k_scan3() {
    __shared__ int tsum[SCAN_TPB];
    int tid = threadIdx.x, blk = blockIdx.x;
    int base = blk * SCAN_CHUNK + tid * SCAN_ELEMS;
    int c[SCAN_ELEMS];
    int s = 0;
#pragma unroll
    for (int i = 0; i < SCAN_ELEMS; i++) {
        int idx = base + i;
        c[i] = (idx < NNODES) ? g_cnt[idx] : 0;
        s += c[i];
    }
    tsum[tid] = s;
    __syncthreads();
    for (int o = 1; o < SCAN_TPB; o <<= 1) {
        int v = (tid >= o) ? tsum[tid - o] : 0;
        __syncthreads();
        tsum[tid] += v;
        __syncthreads();
    }
    int run = g_bsum[blk] + ((tid == 0) ? 0 : tsum[tid - 1]);
#pragma unroll
    for (int i = 0; i < SCAN_ELEMS; i++) {
        int idx = base + i;
        if (idx < NNODES) { g_rowptr[idx] = run; run += c[i]; }
    }
}

__global__ void k_fill(const int* __restrict__ ei) {
    int e = blockIdx.x * blockDim.x + threadIdx.x;
    if (e >= NEDGES) return;
    int r = ei[e];
    int c = ei[NEDGES + e];
    int pos = g_rowptr[r] + atomicAdd(&g_cursor[r], 1);
    g_col[pos] = c;
    g_w[pos] = g_dinv[r] * g_dinv[c];
}

// ---------------- weight prep ----------------
template <int K, int D>
__global__ void k_prepW(const float* __restrict__ W,
                        __nv_bfloat16* __restrict__ Wh,
                        __nv_bfloat16* __restrict__ Wl) {
    int i = blockIdx.x * blockDim.x + threadIdx.x;
    if (i >= K * D) return;
    int n = i / K, k = i % K;
    float v = W[k * D + n];
    __nv_bfloat16 h, l;
    split2(v, h, l);
    Wh[n * K + k] = h;
    Wl[n * K + k] = l;
}

// merged prep for W1, W2, W3 (one launch)
__global__ void k_prepW3x(const float* __restrict__ W1,
                          const float* __restrict__ W2,
                          const float* __restrict__ W3) {
    int i = blockIdx.x * blockDim.x + threadIdx.x;
    const int S1 = HID * HID, S2 = 2 * HID * HID, S3 = 2 * HID * HID + HID * COUT;
    __nv_bfloat16 h, l;
    if (i < S1) {
        int n = i / HID, k = i % HID;
        split2(W1[k * HID + n], h, l);
        g_w1h[n * HID + k] = h; g_w1l[n * HID + k] = l;
    } else if (i < S2) {
        int j = i - S1;
        int n = j / HID, k = j % HID;
        split2(W2[k * HID + n], h, l);
        g_w2h[n * HID + k] = h; g_w2l[n * HID + k] = l;
    } else if (i < S3) {
        int j = i - S2;
        int n = j / HID, k = j % HID;   // D=COUT: n in [0,64)
        split2(W3[k * COUT + n], h, l);
        g_w3h[n * HID + k] = h; g_w3l[n * HID + k] = l;
    }
}

// ---------------- pipelined tensor-core split-bf16 GEMM --------------------
template <int K, int D, bool CONVERT>
__global__ __launch_bounds__(512) void k_tgemm512(const float* __restrict__ Af,
                                                  const __nv_bfloat16* __restrict__ Ah,
                                                  const __nv_bfloat16* __restrict__ Al,
                                                  const __nv_bfloat16* __restrict__ Bh,
                                                  const __nv_bfloat16* __restrict__ Bl,
                                                  __half* __restrict__ C) {
    extern __shared__ __align__(1024) uint8_t smem[];
    const int CK = 64;                   // K elems per chunk
    const int NCH = K / CK;
    const int WN = D / 4;                // 32 (D=128) or 16 (D=64)
    const int NT = WN / 8;               // 4 or 2
    const int STA = 128 * 128;           // 16KB per A buffer
    const int SBB = D * 128;             // B buffer bytes
    const int OFF_B = 4 * STA;

    uint32_t sb = smem_u32(smem);
    int tid = threadIdx.x, wid = tid >> 5, lane = tid & 31;
    int wm = wid & 3, wn = wid >> 2;
    int row0 = wm * 32;
    int col0 = wn * WN;
    int grow = blockIdx.x * 128;

    float acc[2][NT][4];
#pragma unroll
    for (int i = 0; i < 2; i++)
#pragma unroll
        for (int j = 0; j < NT; j++)
#pragma unroll
            for (int q = 0; q < 4; q++) acc[i][j][q] = 0.f;

    float4 pf[4];                        // CONVERT prefetch registers

    auto a_async = [&](int s, int ch) {
        int kk = ch * CK;
#pragma unroll
        for (int i = 0; i < 2; i++) {
            int u = tid + i * 512;
            int m = u >> 3, g = u & 7;
            int r = grow + m;
            int rc = (r < NNODES) ? r : 0;
            int nb = (r < NNODES) ? 16 : 0;
            uint32_t so = sw128((uint32_t)(m * 128 + g * 16));
            cpa16(sb + (2 * s) * STA + so, &Ah[(size_t)rc * K + kk + g * 8], nb);
            cpa16(sb + (2 * s + 1) * STA + so, &Al[(size_t)rc * K + kk + g * 8], nb);
        }
    };
    auto b_async = [&](int s, int ch) {
        int kk = ch * CK;
#pragma unroll
        for (int i = 0; i < (D * 8 + 511) / 512; i++) {
            int u = tid + i * 512;
            if (u < D * 8) {
                int n = u >> 3, g = u & 7;
                uint32_t so = sw128((uint32_t)(n * 128 + g * 16));
                cpa16(sb + OFF_B + (2 * s) * SBB + so, &Bh[n * K + kk + g * 8], 16);
                cpa16(sb + OFF_B + (2 * s + 1) * SBB + so, &Bl[n * K + kk + g * 8], 16);
            }
        }
    };
    auto a_ldregs = [&](int ch) {
        int kk = ch * CK;
#pragma unroll
        for (int i = 0; i < 2; i++) {
            int u = tid + i * 512;
            int m = u >> 3, g = u & 7;
            int r = grow + m;
            pf[2 * i] = make_float4(0.f, 0.f, 0.f, 0.f);
            pf[2 * i + 1] = pf[2 * i];
            if (r < NNODES) {
                const float* p = &Af[(size_t)r * K + kk + g * 8];
                pf[2 * i] = *(const float4*)p;
                pf[2 * i + 1] = *(const float4*)(p + 4);
            }
        }
    };
    auto a_cvtsts = [&](int s) {
#pragma unroll
        for (int i = 0; i < 2; i++) {
            int u = tid + i * 512;
            int m = u >> 3, g = u & 7;
            float f[8] = {pf[2 * i].x, pf[2 * i].y, pf[2 * i].z, pf[2 * i].w,
                          pf[2 * i + 1].x, pf[2 * i + 1].y, pf[2 * i + 1].z, pf[2 * i + 1].w};
            uint32_t hp[4], lp[4];
#pragma unroll
            for (int j = 0; j < 4; j++) {
                __nv_bfloat16 h0, l0, h1, l1;
                split2(f[2 * j], h0, l0);
                split2(f[2 * j + 1], h1, l1);
                hp[j] = (uint32_t)__bfloat16_as_ushort(h0)
                      | ((uint32_t)__bfloat16_as_ushort(h1) << 16);
                lp[j] = (uint32_t)__bfloat16_as_ushort(l0)
                      | ((uint32_t)__bfloat16_as_ushort(l1) << 16);
            }
            uint32_t so = sw128((uint32_t)(m * 128 + g * 16));
            *(uint4*)(smem + (2 * s) * STA + so) = make_uint4(hp[0], hp[1], hp[2], hp[3]);
            *(uint4*)(smem + (2 * s + 1) * STA + so) = make_uint4(lp[0], lp[1], lp[2], lp[3]);
        }
    };

    // ---- prologue: fill stage 0 ----
    if (CONVERT) { a_ldregs(0); a_cvtsts(0); }
    else a_async(0, 0);
    b_async(0, 0);
    cpa_commit();

    // ---- pipelined main loop ----
    for (int ch = 0; ch < NCH; ch++) {
        int cur = ch & 1, nxt = cur ^ 1;
        bool more = (ch + 1 < NCH);
        if (more) {
            if (CONVERT) a_ldregs(ch + 1);     // LDGs in flight during MMA
            else a_async(nxt, ch + 1);
            b_async(nxt, ch + 1);
            cpa_commit();
        }
        if (more) cpa_wait1(); else cpa_wait0();
        __syncthreads();
        {
            uint32_t aB0 = sb + (2 * cur) * STA;
            uint32_t aB1 = sb + (2 * cur + 1) * STA;
            uint32_t bB0 = sb + OFF_B + (2 * cur) * SBB;
            uint32_t bB1 = sb + OFF_B + (2 * cur + 1) * SBB;
#pragma unroll
            for (int k16 = 0; k16 < CK / 16; k16++) {
                int kb = k16 * 32;
                uint32_t ah[2][4], al[2][4];
#pragma unroll
                for (int mt = 0; mt < 2; mt++) {
                    int r = row0 + mt * 16 + (lane & 15);
                    int cb = kb + ((lane & 16) ? 16 : 0);
                    uint32_t so = sw128((uint32_t)(r * 128 + cb));
                    ldsm4(ah[mt], aB0 + so);
                    ldsm4(al[mt], aB1 + so);
                }
#pragma unroll
                for (int bt = 0; bt < NT / 2; bt++) {
                    int n = col0 + bt * 16 + (lane & 7) + ((lane & 16) ? 8 : 0);
                    int cb = kb + ((lane & 8) ? 16 : 0);
                    uint32_t so = sw128((uint32_t)(n * 128 + cb));
                    uint32_t bh[4], bl[4];
                    ldsm4(bh, bB0 + so);
                    ldsm4(bl, bB1 + so);
#pragma unroll
                    for (int h = 0; h < 2; h++) {
                        int nt = bt * 2 + h;
#pragma unroll
                        for (int mt = 0; mt < 2; mt++) {
                            mma16816(acc[mt][nt], ah[mt], &bh[h * 2]);
                            mma16816(acc[mt][nt], ah[mt], &bl[h * 2]);
                            mma16816(acc[mt][nt], al[mt], &bh[h * 2]);
                        }
                    }
                }
            }
        }
        if (more && CONVERT) a_cvtsts(nxt);    // STS after MMA (LDG latency hidden)
        __syncthreads();                       // stage cur free for ch+2 writes
    }

    // ---- epilogue: fragment -> global fp16 (half2 per store)
#pragma unroll
    for (int mt = 0; mt < 2; mt++) {
        int r0 = grow + row0 + mt * 16 + (lane >> 2);
        int r1 = r0 + 8;
#pragma unroll
        for (int nt = 0; nt < NT; nt++) {
            int cc = col0 + nt * 8 + (lane & 3) * 2;
            if (r0 < NNODES)
                *(__half2*)&C[(size_t)r0 * D + cc] =
                    __floats2half2_rn(acc[mt][nt][0], acc[mt][nt][1]);
            if (r1 < NNODES)
                *(__half2*)&C[(size_t)r1 * D + cc] =
                    __floats2half2_rn(acc[mt][nt][2], acc[mt][nt][3]);
        }
    }
}

// ---------------- sparse aggregation (fp16 gather, fp32 accumulate) --------
template <bool PRE>
__global__ void k_agg128s(const __half* __restrict__ tmp,
                          __nv_bfloat16* __restrict__ ah,
                          __nv_bfloat16* __restrict__ al,
                          __nv_bfloat16* __restrict__ ph,
                          __nv_bfloat16* __restrict__ pl) {
    int gw = (blockIdx.x * blockDim.x + threadIdx.x) >> 5;
    int lane = threadIdx.x & 31;
    if (gw >= NNODES) return;
    const uint2* __restrict__ t = (const uint2*)tmp;   // 4 halves per lane
    float di = g_dinv[gw];
    float s = di * di;
    uint2 u = t[gw * 32 + lane];
    float2 p0 = __half22float2(*(__half2*)&u.x);
    float2 p1 = __half22float2(*(__half2*)&u.y);
    float4 acc = make_float4(p0.x * s, p0.y * s, p1.x * s, p1.y * s);
    float4 acc2 = make_float4(0.f, 0.f, 0.f, 0.f);
    int e = g_rowptr[gw], en = g_rowptr[gw + 1];
    for (; e + 3 < en; e += 4) {
        int c0 = g_col[e], c1 = g_col[e + 1], c2 = g_col[e + 2], c3 = g_col[e + 3];
        float w0 = g_w[e], w1 = g_w[e + 1], w2 = g_w[e + 2], w3 = g_w[e + 3];
        uint2 a = t[c0 * 32 + lane];
        uint2 b = t[c1 * 32 + lane];
        uint2 cc = t[c2 * 32 + lane];
        uint2 d = t[c3 * 32 + lane];
        float2 a0 = __half22float2(*(__half2*)&a.x), a1 = __half22float2(*(__half2*)&a.y);
        float2 b0 = __half22float2(*(__half2*)&b.x), b1 = __half22float2(*(__half2*)&b.y);
        float2 c0f = __half22float2(*(__half2*)&cc.x), c1f = __half22float2(*(__half2*)&cc.y);
        float2 d0 = __half22float2(*(__half2*)&d.x), d1 = __half22float2(*(__half2*)&d.y);
        acc.x = fmaf(w0, a0.x, acc.x);   acc.y = fmaf(w0, a0.y, acc.y);
        acc.z = fmaf(w0, a1.x, acc.z);   acc.w = fmaf(w0, a1.y, acc.w);
        acc2.x = fmaf(w1, b0.x, acc2.x); acc2.y = fmaf(w1, b0.y, acc2.y);
        acc2.z = fmaf(w1, b1.x, acc2.z); acc2.w = fmaf(w1, b1.y, acc2.w);
        acc.x = fmaf(w2, c0f.x, acc.x);  acc.y = fmaf(w2, c0f.y, acc.y);
        acc.z = fmaf(w2, c1f.x, acc.z);  acc.w = fmaf(w2, c1f.y, acc.w);
        acc2.x = fmaf(w3, d0.x, acc2.x); acc2.y = fmaf(w3, d0.y, acc2.y);
        acc2.z = fmaf(w3, d1.x, acc2.z); acc2.w = fmaf(w3, d1.y, acc2.w);
    }
    for (; e < en; e++) {
        int c0 = g_col[e];
        float w0 = g_w[e];
        uint2 a = t[c0 * 32 + lane];
        float2 a0 = __half22float2(*(__half2*)&a.x);
        float2 a1 = __half22float2(*(__half2*)&a.y);
        acc.x = fmaf(w0, a0.x, acc.x); acc.y = fmaf(w0, a0.y, acc.y);
        acc.z = fmaf(w0, a1.x, acc.z); acc.w = fmaf(w0, a1.y, acc.w);
    }
    acc.x += acc2.x; acc.y += acc2.y; acc.z += acc2.z; acc.w += acc2.w;

    float f[4] = {acc.x, acc.y, acc.z, acc.w};
    size_t base = (size_t)gw * HID + lane * 4;
    if (PRE) {
        ushort hh[4], ll[4];
#pragma unroll
        for (int j = 0; j < 4; j++) {
            __nv_bfloat16 h, l;
            split2(f[j], h, l);
            hh[j] = __bfloat16_as_ushort(h);
            ll[j] = __bfloat16_as_ushort(l);
        }
        *(uint2*)&ph[base] = make_uint2((uint32_t)hh[0] | ((uint32_t)hh[1] << 16),
                                        (uint32_t)hh[2] | ((uint32_t)hh[3] << 16));
        *(uint2*)&pl[base] = make_uint2((uint32_t)ll[0] | ((uint32_t)ll[1] << 16),
                                        (uint32_t)ll[2] | ((uint32_t)ll[3] << 16));
    }
    ushort rh[4], rl[4];
#pragma unroll
    for (int j = 0; j < 4; j++) {
        float v = fmaxf(f[j], 0.f);
        __nv_bfloat16 h, l;
        split2(v, h, l);
        rh[j] = __bfloat16_as_ushort(h);
        rl[j] = __bfloat16_as_ushort(l);
    }
    *(uint2*)&ah[base] = make_uint2((uint32_t)rh[0] | ((uint32_t)rh[1] << 16),
                                    (uint32_t)rh[2] | ((uint32_t)rh[3] << 16));
    *(uint2*)&al[base] = make_uint2((uint32_t)rl[0] | ((uint32_t)rl[1] << 16),
                                    (uint32_t)rl[2] | ((uint32_t)rl[3] << 16));
}

__global__ void k_agg64h(const __half* __restrict__ tmp, float* __restrict__ out) {
    int gw = (blockIdx.x * blockDim.x + threadIdx.x) >> 5;
    int lane = threadIdx.x & 31;
    if (gw >= NNODES) return;
    const uint32_t* __restrict__ t = (const uint32_t*)tmp;  // 2 halves per lane
    float di = g_dinv[gw];
    float s = di * di;
    uint32_t u = t[gw * 32 + lane];
    float2 p = __half22float2(*(__half2*)&u);
    float2 acc = make_float2(p.x * s, p.y * s);
    float2 acc2 = make_float2(0.f, 0.f);
    int e = g_rowptr[gw], en = g_rowptr[gw + 1];
    for (; e + 3 < en; e += 4) {
        int c0 = g_col[e], c1 = g_col[e + 1], c2 = g_col[e + 2], c3 = g_col[e + 3];
        float w0 = g_w[e], w1 = g_w[e + 1], w2 = g_w[e + 2], w3 = g_w[e + 3];
        uint32_t a = t[c0 * 32 + lane];
        uint32_t b = t[c1 * 32 + lane];
        uint32_t c = t[c2 * 32 + lane];
        uint32_t d = t[c3 * 32 + lane];
        float2 af = __half22float2(*(__half2*)&a);
        float2 bf = __half22float2(*(__half2*)&b);
        float2 cf = __half22float2(*(__half2*)&c);
        float2 df = __half22float2(*(__half2*)&d);
        acc.x = fmaf(w0, af.x, acc.x);   acc.y = fmaf(w0, af.y, acc.y);
        acc2.x = fmaf(w1, bf.x, acc2.x); acc2.y = fmaf(w1, bf.y, acc2.y);
        acc.x = fmaf(w2, cf.x, acc.x);   acc.y = fmaf(w2, cf.y, acc.y);
        acc2.x = fmaf(w3, df.x, acc2.x); acc2.y = fmaf(w3, df.y, acc2.y);
    }
    for (; e < en; e++) {
        int c0 = g_col[e];
        float w0 = g_w[e];
        uint32_t a = t[c0 * 32 + lane];
        float2 af = __half22float2(*(__half2*)&a);
        acc.x = fmaf(w0, af.x, acc.x); acc.y = fmaf(w0, af.y, acc.y);
    }
    acc.x += acc2.x; acc.y += acc2.y;
    ((float2*)out)[gw * 32 + lane] = acc;
}

// ---------------- Gram via mma from pre-split bf16 h2 (D=128) ---------------
__global__ __launch_bounds__(256) void k_gram_split(const __nv_bfloat16* __restrict__ ph,
                                                    const __nv_bfloat16* __restrict__ pl) {
    const int D = HID;
    __shared__ __align__(1024) uint8_t sm[2 * D * 128];
    const int OFF_L = D * 128;
    const int FG = D / 4;
    const int PAIRS = 256 / FG;
    const int NT = D / 8;
    const int MW = D / 16;
    uint32_t sb = smem_u32(sm);
    int tid = threadIdx.x, wid = tid >> 5, lane = tid & 31;
    int f4 = tid % FG;
    int rp0 = tid / FG;

    float acc[NT][4];
#pragma unroll
    for (int j = 0; j < NT; j++)
#pragma unroll
        for (int q = 0; q < 4; q++) acc[j][q] = 0.f;
    float cs0 = 0.f, cs1 = 0.f, cs2 = 0.f, cs3 = 0.f;

    const int NCHUNK = (NNODES + 63) / 64;
    for (int ch = blockIdx.x; ch < NCHUNK; ch += gridDim.x) {
        int rbase = ch * 64;
#pragma unroll
        for (int it = 0; it < 32 / PAIRS; it++) {
            int pr = rp0 + it * PAIRS;
            int r0 = rbase + pr * 2, r1 = r0 + 1;
            uint2 h0v = make_uint2(0, 0), h1v = h0v, l0v = h0v, l1v = h0v;
            if (r0 < NNODES) {
                h0v = *(const uint2*)&ph[(size_t)r0 * D + f4 * 4];
                l0v = *(const uint2*)&pl[(size_t)r0 * D + f4 * 4];
            }
            if (r1 < NNODES) {
                h1v = *(const uint2*)&ph[(size_t)r1 * D + f4 * 4];
                l1v = *(const uint2*)&pl[(size_t)r1 * D + f4 * 4];
            }
            const ushort* h0s = (const ushort*)&h0v;
            const ushort* h1s = (const ushort*)&h1v;
            const ushort* l0s = (const ushort*)&l0v;
            const ushort* l1s = (const ushort*)&l1v;
            float fs[4];
#pragma unroll
            for (int j = 0; j < 4; j++) {
                fs[j] = __bfloat162float(__ushort_as_bfloat16(h0s[j]))
                      + __bfloat162float(__ushort_as_bfloat16(l0s[j]))
                      + __bfloat162float(__ushort_as_bfloat16(h1s[j]))
                      + __bfloat162float(__ushort_as_bfloat16(l1s[j]));
                int feat = f4 * 4 + j;
                uint32_t hp = (uint32_t)h0s[j] | ((uint32_t)h1s[j] << 16);
                uint32_t lp = (uint32_t)l0s[j] | ((uint32_t)l1s[j] << 16);
                uint32_t so = sw128((uint32_t)(feat * 128 + pr * 4));
                *(uint32_t*)(sm + so) = hp;
                *(uint32_t*)(sm + OFF_L + so) = lp;
            }
            cs0 += fs[0]; cs1 += fs[1]; cs2 += fs[2]; cs3 += fs[3];
        }
        __syncthreads();
        if (wid < MW) {
#pragma unroll
            for (int k16 = 0; k16 < 4; k16++) {
                int kb = k16 * 32;
                uint32_t ah[4], al[4];
                {
                    int r = wid * 16 + (lane & 15);
                    int cb = kb + ((lane & 16) ? 16 : 0);
                    uint32_t so = sw128((uint32_t)(r * 128 + cb));
                    ldsm4(ah, sb + so);
                    ldsm4(al, sb + OFF_L + so);
                }
#pragma unroll
                for (int bt = 0; bt < NT / 2; bt++) {
                    int n = bt * 16 + (lane & 7) + ((lane & 16) ? 8 : 0);
                    int cb = kb + ((lane & 8) ? 16 : 0);
                    uint32_t so = sw128((uint32_t)(n * 128 + cb));
                    uint32_t bh[4], bl[4];
                    ldsm4(bh, sb + so);
                    ldsm4(bl, sb + OFF_L + so);
#pragma unroll
                    for (int hh = 0; hh < 2; hh++) {
                        int nt = bt * 2 + hh;
                        mma16816(acc[nt], ah, &bh[hh * 2]);
                        mma16816(acc[nt], ah, &bl[hh * 2]);
                        mma16816(acc[nt], al, &bh[hh * 2]);
                    }
                }
            }
        }
        __syncthreads();
    }
    if (wid < MW) {
        int mrow = wid * 16 + (lane >> 2);
#pragma unroll
        for (int nt = 0; nt < NT; nt++) {
            int c = nt * 8 + (lane & 3) * 2;
            atomicAdd(&g_G[mrow * D + c], acc[nt][0]);
            atomicAdd(&g_G[mrow * D + c + 1], acc[nt][1]);
            atomicAdd(&g_G[(mrow + 8) * D + c], acc[nt][2]);
            atomicAdd(&g_G[(mrow + 8) * D + c + 1], acc[nt][3]);
        }
    }
    atomicAdd(&g_csum[f4 * 4 + 0], cs0);
    atomicAdd(&g_csum[f4 * 4 + 1], cs1);
    atomicAdd(&g_csum[f4 * 4 + 2], cs2);
    atomicAdd(&g_csum[f4 * 4 + 3], cs3);
}

// ---------------- Gram via mma from fp32 (D=64, for h3/out) -----------------
template <int D>
__global__ __launch_bounds__(256) void k_gram_mma(const float* __restrict__ h) {
    __shared__ __align__(1024) uint8_t sm[2 * D * 128];
    const int OFF_L = D * 128;
    const int FG = D / 4;
    const int PAIRS = 256 / FG;
    const int NT = D / 8;
    const int MW = D / 16;
    uint32_t sb = smem_u32(sm);
    int tid = threadIdx.x, wid = tid >> 5, lane = tid & 31;
    int f4 = tid % FG;
    int rp0 = tid / FG;

    float acc[NT][4];
#pragma unroll
    for (int j = 0; j < NT; j++)
#pragma unroll
        for (int q = 0; q < 4; q++) acc[j][q] = 0.f;
    float cs0 = 0.f, cs1 = 0.f, cs2 = 0.f, cs3 = 0.f;

    const int NCHUNK = (NNODES + 63) / 64;
    for (int ch = blockIdx.x; ch < NCHUNK; ch += gridDim.x) {
        int rbase = ch * 64;
#pragma unroll
        for (int it = 0; it < 32 / PAIRS; it++) {
            int pr = rp0 + it * PAIRS;
            int r0 = rbase + pr * 2, r1 = r0 + 1;
            float4 v0 = make_float4(0.f, 0.f, 0.f, 0.f), v1 = v0;
            if (r0 < NNODES) v0 = *(const float4*)&h[(size_t)r0 * D + f4 * 4];
            if (r1 < NNODES) v1 = *(const float4*)&h[(size_t)r1 * D + f4 * 4];
            cs0 += v0.x + v1.x; cs1 += v0.y + v1.y;
            cs2 += v0.z + v1.z; cs3 += v0.w + v1.w;
            float a0[4] = {v0.x, v0.y, v0.z, v0.w};
            float a1[4] = {v1.x, v1.y, v1.z, v1.w};
#pragma unroll
            for (int j = 0; j < 4; j++) {
                int feat = f4 * 4 + j;
                __nv_bfloat16 h0, l0, h1, l1;
                split2(a0[j], h0, l0);
                split2(a1[j], h1, l1);
                uint32_t hp = (uint32_t)__bfloat16_as_ushort(h0)
                            | ((uint32_t)__bfloat16_as_ushort(h1) << 16);
                uint32_t lp = (uint32_t)__bfloat16_as_ushort(l0)
                            | ((uint32_t)__bfloat16_as_ushort(l1) << 16);
                uint32_t so = sw128((uint32_t)(feat * 128 + pr * 4));
                *(uint32_t*)(sm + so) = hp;
                *(uint32_t*)(sm + OFF_L + so) = lp;
            }
        }
        __syncthreads();
        if (wid < MW) {
#pragma unroll
            for (int k16 = 0; k16 < 4; k16++) {
                int kb = k16 * 32;
                uint32_t ah[4], al[4];
                {
                    int r = wid * 16 + (lane & 15);
                    int cb = kb + ((lane & 16) ? 16 : 0);
                    uint32_t so = sw128((uint32_t)(r * 128 + cb));
                    ldsm4(ah, sb + so);
                    ldsm4(al, sb + OFF_L + so);
                }
#pragma unroll
                for (int bt = 0; bt < NT / 2; bt++) {
                    int n = bt * 16 + (lane & 7) + ((lane & 16) ? 8 : 0);
                    int cb = kb + ((lane & 8) ? 16 : 0);
                    uint32_t so = sw128((uint32_t)(n * 128 + cb));
                    uint32_t bh[4], bl[4];
                    ldsm4(bh, sb + so);
                    ldsm4(bl, sb + OFF_L + so);
#pragma unroll
                    for (int hh = 0; hh < 2; hh++) {
                        int nt = bt * 2 + hh;
                        mma16816(acc[nt], ah, &bh[hh * 2]);
                        mma16816(acc[nt], ah, &bl[hh * 2]);
                        mma16816(acc[nt], al, &bh[hh * 2]);
                    }
                }
            }
        }
        __syncthreads();
    }
    if (wid < MW) {
        int mrow = wid * 16 + (lane >> 2);
#pragma unroll
        for (int nt = 0; nt < NT; nt++) {
            int c = nt * 8 + (lane & 3) * 2;
            atomicAdd(&g_G[mrow * D + c], acc[nt][0]);
            atomicAdd(&g_G[mrow * D + c + 1], acc[nt][1]);
            atomicAdd(&g_G[(mrow + 8) * D + c], acc[nt][2]);
            atomicAdd(&g_G[(mrow + 8) * D + c + 1], acc[nt][3]);
        }
    }
    atomicAdd(&g_csum[f4 * 4 + 0], cs0);
    atomicAdd(&g_csum[f4 * 4 + 1], cs1);
    atomicAdd(&g_csum[f4 * 4 + 2], cs2);
    atomicAdd(&g_csum[f4 * 4 + 3], cs3);
}

// ---------------- correlation metric finalize (single block) ----------------
template <int D>
__global__ void k_finalize(float* __restrict__ dst) {
    __shared__ float sd[D];
    __shared__ float red[256];
    int tid = threadIdx.x;
    const float invN = 1.0f / (float)NNODES;
    if (tid < D) {
        float cjj = g_G[tid * D + tid] - g_csum[tid] * g_csum[tid] * invN;
        sd[tid] = sqrtf(fmaxf(cjj, 1e-12f));
    }
    __syncthreads();
    float sum = 0.f;
    for (int idx = tid; idx < D * D; idx += 256) {
        int j = idx / D, k = idx % D;
        if (k > j) {
            float cov = g_G[idx] - g_csum[j] * g_csum[k] * invN;
            sum += fabsf(cov / (sd[j] * sd[k]));
        }
    }
    red[tid] = sum;
    __syncthreads();
    for (int off = 128; off > 0; off >>= 1) {
        if (tid < off) red[tid] += red[tid + off];
        __syncthreads();
    }
    if (tid == 0) *dst = red[0] / (float)(D * (D - 1) / 2);
}

// ---------------- launch ----------------
extern "C" void kernel_launch(void* const* d_in, const int* in_sizes, int n_in,
                              void* d_out, int out_size) {
    const float* x  = (const float*)d_in[0];
    const int*   ei = (const int*)d_in[1];
    const float* W0 = (const float*)d_in[2];
    const float* W1 = (const float*)d_in[3];
    const float* W2 = (const float*)d_in[4];
    const float* W3 = (const float*)d_in[5];
    float* out = (float*)d_out;

    __half* tmp;
    __nv_bfloat16 *ah, *al, *ph, *pl;
    cudaGetSymbolAddress((void**)&tmp, g_tmp);
    cudaGetSymbolAddress((void**)&ah, g_ah);
    cudaGetSymbolAddress((void**)&al, g_al);
    cudaGetSymbolAddress((void**)&ph, g_ph);
    cudaGetSymbolAddress((void**)&pl, g_pl);
    __nv_bfloat16 *w0h, *w0l, *w1h, *w1l, *w2h, *w2l, *w3h, *w3l;
    cudaGetSymbolAddress((void**)&w0h, g_w0h); cudaGetSymbolAddress((void**)&w0l, g_w0l);
    cudaGetSymbolAddress((void**)&w1h, g_w1h); cudaGetSymbolAddress((void**)&w1l, g_w1l);
    cudaGetSymbolAddress((void**)&w2h, g_w2h); cudaGetSymbolAddress((void**)&w2l, g_w2l);
    cudaGetSymbolAddress((void**)&w3h, g_w3h); cudaGetSymbolAddress((void**)&w3l, g_w3l);

    const int SM_BIG = 4 * 128 * 128 + 4 * HID * 128;   // 131072 (2 stages)
    const int SM_SML = 4 * 128 * 128 + 4 * COUT * 128;  // 98304
    cudaFuncSetAttribute(k_tgemm512<FIN, HID, true>,
                         cudaFuncAttributeMaxDynamicSharedMemorySize, SM_BIG);
    cudaFuncSetAttribute(k_tgemm512<HID, HID, false>,
                         cudaFuncAttributeMaxDynamicSharedMemorySize, SM_BIG);
    cudaFuncSetAttribute(k_tgemm512<HID, COUT, false>,
                         cudaFuncAttributeMaxDynamicSharedMemorySize, SM_SML);

    // side stream + events for fork/join inside graph capture.
    // NOT destroyed: destroying a capture-participant stream invalidates the
    // capture; kernel_launch is called O(2) times so the leak is bounded.
    cudaStream_t s1;
    cudaStreamCreateWithFlags(&s1, cudaStreamNonBlocking);
    cudaEvent_t eFork1, ePre, eFork2, eCorr;
    cudaEventCreateWithFlags(&eFork1, cudaEventDisableTiming);
    cudaEventCreateWithFlags(&ePre,  cudaEventDisableTiming);
    cudaEventCreateWithFlags(&eFork2, cudaEventDisableTiming);
    cudaEventCreateWithFlags(&eCorr, cudaEventDisableTiming);

    const int TB = 256;
    const int nbN = (NNODES + TB - 1) / TB;
    const int nbE = (NEDGES + TB - 1) / TB;
    const int nbM = (NNODES + 127) / 128;        // GEMM blocks (128 rows)
    const int nbA = (NNODES + 7) / 8;            // agg blocks (8 warps/block)
    const int P3N = 2 * HID * HID + HID * COUT;  // merged prepW elems

    // ---- fork: preprocessing chain on s1, L0 GEMM path on capture stream ----
    cudaEventRecord(eFork1, 0);
    cudaStreamWaitEvent(s1, eFork1, 0);

    k_prepW<FIN, HID><<<(FIN * HID + TB - 1) / TB, TB>>>(W0, w0h, w0l);      // idx0 (s0)
    k_zero_init<<<nbN, TB, 0, s1>>>();                                        // idx1 (s1)
    k_count<<<nbE, TB, 0, s1>>>(ei);                                          // idx2 (s1)
    k_tgemm512<FIN, HID, true><<<nbM, 512, SM_BIG>>>(x, nullptr, nullptr,
                                                     w0h, w0l, tmp);          // idx3 (s0, profiled)
    k_scan1<<<SCAN_NB, SCAN_TPB, 0, s1>>>();       // also computes dinv
    k_scan2<<<1, 64, 0, s1>>>();
    k_scan3<<<SCAN_NB, SCAN_TPB, 0, s1>>>();
    k_fill<<<nbE, TB, 0, s1>>>(ei);
    k_prepW3x<<<(P3N + TB - 1) / TB, TB, 0, s1>>>(W1, W2, W3);
    cudaEventRecord(ePre, s1);

    // ---- join: aggregation needs CSR + dinv; GEMM1 needs prepW1 ----
    cudaStreamWaitEvent(0, ePre, 0);

    // layer 0 aggregation -> relu'd split h0
    k_agg128s<false><<<nbA, TB>>>(tmp, ah, al, ph, pl);
    // layer 1
    k_tgemm512<HID, HID, false><<<nbM, 512, SM_BIG>>>(nullptr, ah, al, w1h, w1l, tmp);
    k_agg128s<false><<<nbA, TB>>>(tmp, ah, al, ph, pl);
    // layer 2 (pre-relu h2 kept for corr_2)
    k_tgemm512<HID, HID, false><<<nbM, 512, SM_BIG>>>(nullptr, ah, al, w2h, w2l, tmp);
    k_agg128s<true><<<nbA, TB>>>(tmp, ah, al, ph, pl);

    // ---- fork: corr_2 metric (s1) runs concurrent with layer-3 chain (s0) ----
    cudaEventRecord(eFork2, 0);
    cudaStreamWaitEvent(s1, eFork2, 0);
    k_zero_G<<<(HID * HID + TB - 1) / TB, TB, 0, s1>>>();
    k_gram_split<<<296, 256, 0, s1>>>(ph, pl);
    k_finalize<HID><<<1, 256, 0, s1>>>(out + NNODES * COUT);
    cudaEventRecord(eCorr, s1);

    // layer 3: relu(h2) @ W3 -> agg directly into d_out (capture stream)
    k_tgemm512<HID, COUT, false><<<nbM, 512, SM_SML>>>(nullptr, ah, al, w3h, w3l, tmp);
    k_agg64h<<<nbA, TB>>>(tmp, out);

    // ---- join: gram64 needs g_G freed by finalize<HID> and out from agg64 ----
    cudaStreamWaitEvent(0, eCorr, 0);
    k_zero_G<<<(HID * HID + TB - 1) / TB, TB>>>();
    k_gram_mma<COUT><<<296, 256>>>(out);
    k_finalize<COUT><<<1, 256>>>(out + NNODES * COUT + 1);
}